// round 2
// baseline (speedup 1.0000x reference)
#include <cuda_runtime.h>
#include <math.h>

#define Bb 64
#define Ss 400
#define Hh 1024
#define Ee 300
#define Vv 50000
#define NOOV 50
#define VE 50050
#define NEGINF (-1e12f)

// ---------------- scratch (static device globals; no allocations) ----------------
__device__ float    g_pooled_raw[Bb*Hh];
__device__ float    g_pooled_feat[Bb*Hh];
__device__ float    g_catA1[Bb*1624];
__device__ float    g_combined[Bb*Ee];
__device__ float    g_catA2[Bb*1324];
__device__ float    g_x[Bb*Ee];
__device__ float    g_gates[Bb*4*Hh];
__device__ float    g_h[Bb*Hh];
__device__ float    g_gvec[Bb*Hh];
__device__ float    g_energy[Bb*Ss];
__device__ float    g_wsum[Bb*Hh];
__device__ float    g_context[Bb*Hh];
__device__ float    g_catHC[Bb*2*Hh];
__device__ float    g_logit_in[Bb*Hh];
__device__ float    g_logit[(size_t)Bb*Vv];
__device__ unsigned g_scat[(size_t)Bb*VE];

// monotone float<->uint order-preserving encoding (for atomicMax on floats)
__device__ __forceinline__ unsigned fenc(float f) {
    unsigned u = __float_as_uint(f);
    return (u & 0x80000000u) ? ~u : (u | 0x80000000u);
}
__device__ __forceinline__ float fdec(unsigned u) {
    return (u & 0x80000000u) ? __uint_as_float(u & 0x7fffffffu) : __uint_as_float(~u);
}
__device__ __forceinline__ float sigmf(float x) { return 1.f / (1.f + expf(-x)); }

// ---------------- generic tiled SGEMM: C[M,N] = A[M,K] @ B[K,N] (+bias)(+acc)(+tanh) ----------------
// EPI: 0 = none, 1 = tanhf
// TRANSB: B stored row-major as (N,K), i.e. C += A[m,k]*B[n,k]
template<int EPI, bool TRANSB>
__global__ void gemm_kernel(const float* __restrict__ A, const float* __restrict__ Bm,
                            const float* __restrict__ bias, float* __restrict__ C,
                            int M, int N, int K, int accflag)
{
    constexpr int BM = 64, BN = 128, BK = 16, TM = 4, TN = 8;
    __shared__ __align__(16) float As[BK][BM];
    __shared__ __align__(16) float Bs[BK][BN];

    const int tid = threadIdx.x;          // 256 threads
    const int tx  = tid & 15;             // 0..15
    const int ty  = tid >> 4;             // 0..15
    const int bn0 = blockIdx.x * BN;
    const int bm0 = blockIdx.y * BM;

    float acc[TM][TN];
#pragma unroll
    for (int j = 0; j < TM; j++)
#pragma unroll
        for (int l = 0; l < TN; l++) acc[j][l] = 0.f;

    for (int k0 = 0; k0 < K; k0 += BK) {
        // load A tile (BM x BK), 4 elems/thread
#pragma unroll
        for (int j = 0; j < 4; j++) {
            int i = tid + j * 256;
            int m = i / BK, k = i % BK;
            int gm = bm0 + m, gk = k0 + k;
            As[k][m] = (gm < M && gk < K) ? A[(size_t)gm * K + gk] : 0.f;
        }
        // load B tile (BK x BN), 8 elems/thread
#pragma unroll
        for (int j = 0; j < 8; j++) {
            int i = tid + j * 256;
            if (TRANSB) {
                int n = i / BK, k = i % BK;
                int gn = bn0 + n, gk = k0 + k;
                Bs[k][n] = (gn < N && gk < K) ? Bm[(size_t)gn * K + gk] : 0.f;
            } else {
                int k = i / BN, n = i % BN;
                int gk = k0 + k, gn = bn0 + n;
                Bs[k][n] = (gk < K && gn < N) ? Bm[(size_t)gk * N + gn] : 0.f;
            }
        }
        __syncthreads();

#pragma unroll
        for (int k = 0; k < BK; k++) {
            float a[TM], b[TN];
            float4 av = *reinterpret_cast<const float4*>(&As[k][ty * TM]);
            a[0] = av.x; a[1] = av.y; a[2] = av.z; a[3] = av.w;
            float4 bv0 = *reinterpret_cast<const float4*>(&Bs[k][tx * TN]);
            float4 bv1 = *reinterpret_cast<const float4*>(&Bs[k][tx * TN + 4]);
            b[0] = bv0.x; b[1] = bv0.y; b[2] = bv0.z; b[3] = bv0.w;
            b[4] = bv1.x; b[5] = bv1.y; b[6] = bv1.z; b[7] = bv1.w;
#pragma unroll
            for (int j = 0; j < TM; j++)
#pragma unroll
                for (int l = 0; l < TN; l++) acc[j][l] += a[j] * b[l];
        }
        __syncthreads();
    }

#pragma unroll
    for (int j = 0; j < TM; j++) {
        int gm = bm0 + ty * TM + j;
        if (gm >= M) continue;
#pragma unroll
        for (int l = 0; l < TN; l++) {
            int gn = bn0 + tx * TN + l;
            if (gn >= N) continue;
            float v = acc[j][l];
            if (bias) v += bias[gn];
            if (accflag) v += C[(size_t)gm * N + gn];
            if (EPI == 1) v = tanhf(v);
            C[(size_t)gm * N + gn] = v;
        }
    }
}

// ---------------- pooled_raw[b,h] = mean_s enc[b,s,h] ----------------
__global__ void pool_kernel(const float* __restrict__ enc, float* __restrict__ out)
{
    int b = blockIdx.y;
    int h = blockIdx.x * 256 + threadIdx.x;
    const float* p = enc + (size_t)b * Ss * Hh + h;
    float a0 = 0.f, a1 = 0.f, a2 = 0.f, a3 = 0.f;
    for (int s = 0; s < Ss; s += 4) {
        a0 += p[(size_t)(s + 0) * Hh];
        a1 += p[(size_t)(s + 1) * Hh];
        a2 += p[(size_t)(s + 2) * Hh];
        a3 += p[(size_t)(s + 3) * Hh];
    }
    out[b * Hh + h] = (a0 + a1 + a2 + a3) * (1.0f / Ss);
}

// ---------------- pack kernels ----------------
__global__ void pack1_kernel(const int* __restrict__ y, const float* __restrict__ emb,
                             const float* __restrict__ pooled, const float* __restrict__ dec,
                             float* __restrict__ out)
{
    int b = blockIdx.x;
    int yy = y[b];
    for (int i = threadIdx.x; i < 1624; i += blockDim.x) {
        float v;
        if (i < Ee)           v = emb[(size_t)yy * Ee + i];
        else if (i < Ee + Hh) v = pooled[b * Hh + (i - Ee)];
        else                  v = dec[b * Ee + (i - Ee - Hh)];
        out[b * 1624 + i] = v;
    }
}

__global__ void pack2_kernel(const float* __restrict__ comb, const float* __restrict__ pctx,
                             float* __restrict__ out)
{
    int b = blockIdx.x;
    for (int i = threadIdx.x; i < 1324; i += blockDim.x)
        out[b * 1324 + i] = (i < Ee) ? comb[b * Ee + i] : pctx[b * Hh + (i - Ee)];
}

__global__ void pack3_kernel(const float* __restrict__ h, const float* __restrict__ ctx,
                             float* __restrict__ out, float* __restrict__ dctx)
{
    int b = blockIdx.x;
    for (int i = threadIdx.x; i < 2 * Hh; i += blockDim.x) {
        float v = (i < Hh) ? h[b * Hh + i] : ctx[b * Hh + (i - Hh)];
        out[b * 2 * Hh + i] = v;
        if (i >= Hh) dctx[b * Hh + (i - Hh)] = v;
    }
}

// ---------------- LSTM pointwise ----------------
__global__ void lstm_kernel(const float* __restrict__ gates, const float* __restrict__ c0,
                            float* __restrict__ hs, float* __restrict__ dh, float* __restrict__ dc)
{
    int idx = blockIdx.x * 256 + threadIdx.x;
    if (idx >= Bb * Hh) return;
    int b = idx >> 10, j = idx & (Hh - 1);
    const float* gb = gates + (size_t)b * 4 * Hh;
    float gi = gb[j], gf = gb[Hh + j], gg = gb[2 * Hh + j], go = gb[3 * Hh + j];
    float c = sigmf(gf) * c0[idx] + sigmf(gi) * tanhf(gg);
    float h = sigmf(go) * tanhf(c);
    hs[idx] = h; dh[idx] = h; dc[idx] = c;
}

// ---------------- fused attention per batch row ----------------
// energy[b,s] = g[b]·enc[b,s] + h[b]·b_enc  (masked -> -1e12)
// softmax over s; wsum[b,:] = Sum_s attn[s] * enc[b,s,:]
// NOTE: mask is a 4-byte-per-element array (bool marshaled as int32/float32);
// "masked" == word != 0 (covers both int 1 and float 1.0 bit patterns).
__global__ void attention_kernel(const float* __restrict__ enc, const float* __restrict__ gv,
                                 const float* __restrict__ hv, const float* __restrict__ benc,
                                 const unsigned int* __restrict__ mask,
                                 float* __restrict__ energy_out, float* __restrict__ wsum)
{
    int b = blockIdx.x;
    int tid = threadIdx.x;                 // 512 threads
    int warp = tid >> 5, lane = tid & 31;
    __shared__ float gsh[Hh];
    __shared__ float esh[Ss];
    __shared__ float red[16];
    __shared__ float sh_hb, sh_mx, sh_sum;

    gsh[tid]       = gv[b * Hh + tid];
    gsh[tid + 512] = gv[b * Hh + tid + 512];

    // hb = dot(h[b], b_enc)
    float p = hv[b * Hh + tid] * benc[tid] + hv[b * Hh + tid + 512] * benc[tid + 512];
    for (int o = 16; o; o >>= 1) p += __shfl_xor_sync(0xffffffffu, p, o);
    if (lane == 0) red[warp] = p;
    __syncthreads();
    if (warp == 0) {
        float v = (lane < 16) ? red[lane] : 0.f;
        for (int o = 8; o; o >>= 1) v += __shfl_xor_sync(0xffffffffu, v, o);
        if (lane == 0) sh_hb = v;
    }
    __syncthreads();
    float hb = sh_hb;

    const float* eb = enc + (size_t)b * Ss * Hh;
    // phase 1: energies (one s per warp at a time)
    for (int s = warp; s < Ss; s += 16) {
        const float* row = eb + (size_t)s * Hh;
        float acc = 0.f;
#pragma unroll 8
        for (int i = lane; i < Hh; i += 32) acc += row[i] * gsh[i];
        for (int o = 16; o; o >>= 1) acc += __shfl_xor_sync(0xffffffffu, acc, o);
        if (lane == 0) {
            float e = (mask[b * Ss + s] != 0u) ? NEGINF : (acc + hb);
            esh[s] = e;
            energy_out[b * Ss + s] = e;
        }
    }
    __syncthreads();

    // phase 2: softmax (max)
    float m = (tid < Ss) ? esh[tid] : -3.4e38f;
    for (int o = 16; o; o >>= 1) m = fmaxf(m, __shfl_xor_sync(0xffffffffu, m, o));
    if (lane == 0) red[warp] = m;
    __syncthreads();
    if (warp == 0) {
        float v = (lane < 16) ? red[lane] : -3.4e38f;
        for (int o = 8; o; o >>= 1) v = fmaxf(v, __shfl_xor_sync(0xffffffffu, v, o));
        if (lane == 0) sh_mx = v;
    }
    __syncthreads();
    float mx = sh_mx;

    float sm = 0.f;
    if (tid < Ss) { float pe = expf(esh[tid] - mx); esh[tid] = pe; sm = pe; }
    __syncthreads();
    for (int o = 16; o; o >>= 1) sm += __shfl_xor_sync(0xffffffffu, sm, o);
    if (lane == 0) red[warp] = sm;
    __syncthreads();
    if (warp == 0) {
        float v = (lane < 16) ? red[lane] : 0.f;
        for (int o = 8; o; o >>= 1) v += __shfl_xor_sync(0xffffffffu, v, o);
        if (lane == 0) sh_sum = v;
    }
    __syncthreads();
    float inv = 1.f / sh_sum;

    // phase 3: weighted sum over s (coalesced over h)
    float a0 = 0.f, a1 = 0.f;
    for (int s = 0; s < Ss; s++) {
        float a = esh[s];
        a0 += a * eb[(size_t)s * Hh + tid];
        a1 += a * eb[(size_t)s * Hh + tid + 512];
    }
    wsum[b * Hh + tid]       = a0 * inv;
    wsum[b * Hh + tid + 512] = a1 * inv;
}

// ---------------- scatter-max machinery ----------------
__global__ void init_scat_kernel(unsigned* __restrict__ scat)
{
    size_t idx = (size_t)blockIdx.x * 256 + threadIdx.x;
    if (idx < (size_t)Bb * VE) scat[idx] = fenc(NEGINF);
}

__global__ void scatter_kernel(const float* __restrict__ energy, const int* __restrict__ ext_x,
                               unsigned* __restrict__ scat)
{
    int b = blockIdx.x;
    int s = threadIdx.x;
    if (s < Ss) {
        float e = energy[b * Ss + s];
        int tok = ext_x[b * Ss + s];
        atomicMax(&scat[(size_t)b * VE + tok], fenc(e));
    }
}

__global__ void combine_kernel(const float* __restrict__ logit, const unsigned* __restrict__ scat,
                               float* __restrict__ out)
{
    size_t idx = (size_t)blockIdx.x * 256 + threadIdx.x;
    if (idx >= (size_t)Bb * VE) return;
    int b = (int)(idx / VE), v = (int)(idx % VE);
    float base = (v < Vv) ? logit[(size_t)b * Vv + v] : 0.f;
    float sc = fdec(scat[idx]);
    if (sc == NEGINF) sc = 0.f;
    float o = base + sc;
    if (o == NEGINF) o = 0.f;
    if (v == 1) o = NEGINF;   // UNK_ID
    out[idx] = o;
}

// ---------------- host orchestration ----------------
extern "C" void kernel_launch(void* const* d_in, const int* in_sizes, int n_in,
                              void* d_out, int out_size)
{
    const int*   y        = (const int*)d_in[0];
    const int*   ext_x    = (const int*)d_in[1];
    const float* prev_h   = (const float*)d_in[2];   // (1,B,H)
    const float* prev_c   = (const float*)d_in[3];
    const float* prev_ctx = (const float*)d_in[4];   // (B,1,H)
    const float* enc      = (const float*)d_in[5];   // (B,S,H)
    const unsigned int* mask = (const unsigned int*)d_in[6]; // bool marshaled 4B (B,S)
    const float* dec_out  = (const float*)d_in[7];   // (B,1,E)
    const float* emb      = (const float*)d_in[8];   // (V,E)
    const float* W_enc    = (const float*)d_in[9];   // (H,H)
    const float* b_enc    = (const float*)d_in[10];
    const float* W_comb   = (const float*)d_in[11];  // (1624,300)
    const float* b_comb   = (const float*)d_in[12];
    const float* W_red    = (const float*)d_in[13];  // (1324,300)
    const float* b_red    = (const float*)d_in[14];
    const float* W_ih     = (const float*)d_in[15];  // (300,4096)
    const float* W_hh     = (const float*)d_in[16];  // (1024,4096)
    const float* b_ih     = (const float*)d_in[17];
    const float* b_hh     = (const float*)d_in[18];
    const float* W_cat    = (const float*)d_in[19];  // (2048,1024)
    const float* b_cat    = (const float*)d_in[20];
    const float* W_logit  = (const float*)d_in[21];  // (1024,50000)
    const float* b_logit  = (const float*)d_in[22];
    float* out = (float*)d_out;

    float *pooled_raw, *pooled_feat, *catA1, *combined, *catA2, *xv, *gates, *hs;
    float *gvec, *energy, *wsum, *context, *catHC, *logit_in, *logit;
    unsigned* scat;
    cudaGetSymbolAddress((void**)&pooled_raw,  g_pooled_raw);
    cudaGetSymbolAddress((void**)&pooled_feat, g_pooled_feat);
    cudaGetSymbolAddress((void**)&catA1,       g_catA1);
    cudaGetSymbolAddress((void**)&combined,    g_combined);
    cudaGetSymbolAddress((void**)&catA2,       g_catA2);
    cudaGetSymbolAddress((void**)&xv,          g_x);
    cudaGetSymbolAddress((void**)&gates,       g_gates);
    cudaGetSymbolAddress((void**)&hs,          g_h);
    cudaGetSymbolAddress((void**)&gvec,        g_gvec);
    cudaGetSymbolAddress((void**)&energy,      g_energy);
    cudaGetSymbolAddress((void**)&wsum,        g_wsum);
    cudaGetSymbolAddress((void**)&context,     g_context);
    cudaGetSymbolAddress((void**)&catHC,       g_catHC);
    cudaGetSymbolAddress((void**)&logit_in,    g_logit_in);
    cudaGetSymbolAddress((void**)&logit,       g_logit);
    cudaGetSymbolAddress((void**)&scat,        g_scat);

    const size_t O1 = (size_t)Bb * VE;              // h
    const size_t O2 = O1 + (size_t)Bb * Hh;         // c
    const size_t O3 = O2 + (size_t)Bb * Hh;         // context

    // scat init early (independent of everything else)
    init_scat_kernel<<<(Bb * VE + 255) / 256, 256>>>(scat);

    // 1) pool encoder outputs over S
    pool_kernel<<<dim3(Hh / 256, Bb), 256>>>(enc, pooled_raw);
    // 2) pooled_feat = pooled_raw @ W_enc + b_enc   (64x1024x1024)
    gemm_kernel<0, false><<<dim3(8, 1), 256>>>(pooled_raw, W_enc, b_enc, pooled_feat, Bb, Hh, Hh, 0);
    // 3) catA1 = [emb[y], pooled_feat, decoder_out]
    pack1_kernel<<<Bb, 256>>>(y, emb, pooled_feat, dec_out, catA1);
    // 4) combined = catA1 @ W_comb + b_comb  (64x300x1624)
    gemm_kernel<0, false><<<dim3(3, 1), 256>>>(catA1, W_comb, b_comb, combined, Bb, Ee, 1624, 0);
    // 5) catA2 = [combined, prev_context]
    pack2_kernel<<<Bb, 256>>>(combined, prev_ctx, catA2);
    // 6) x = catA2 @ W_red + b_red  (64x300x1324)
    gemm_kernel<0, false><<<dim3(3, 1), 256>>>(catA2, W_red, b_red, xv, Bb, Ee, 1324, 0);
    // 7) gates = x @ W_ih + b_ih ; gates += h0 @ W_hh + b_hh
    gemm_kernel<0, false><<<dim3(32, 1), 256>>>(xv, W_ih, b_ih, gates, Bb, 4 * Hh, Ee, 0);
    gemm_kernel<0, false><<<dim3(32, 1), 256>>>(prev_h, W_hh, b_hh, gates, Bb, 4 * Hh, Hh, 1);
    // 8) LSTM pointwise -> h (scratch + d_out), c (d_out)
    lstm_kernel<<<(Bb * Hh + 255) / 256, 256>>>(gates, prev_c, hs, out + O1, out + O2);
    // 9) g[b,:] = h[b] @ W_enc^T   (TRANSB)
    gemm_kernel<0, true><<<dim3(8, 1), 256>>>(hs, W_enc, nullptr, gvec, Bb, Hh, Hh, 0);
    // 10) fused attention: energy (masked), softmax, weighted enc sum
    attention_kernel<<<Bb, 512>>>(enc, gvec, hs, b_enc, mask, energy, wsum);
    // 11) context = wsum @ W_enc + b_enc
    gemm_kernel<0, false><<<dim3(8, 1), 256>>>(wsum, W_enc, b_enc, context, Bb, Hh, Hh, 0);
    // 12) catHC = [h, context]; also writes context to d_out
    pack3_kernel<<<Bb, 256>>>(hs, context, catHC, out + O3);
    // 13) logit_in = tanh(catHC @ W_cat + b_cat)  (64x1024x2048)
    gemm_kernel<1, false><<<dim3(8, 1), 256>>>(catHC, W_cat, b_cat, logit_in, Bb, Hh, 2 * Hh, 0);
    // 14) logit = logit_in @ W_logit + b_logit   (64x50000x1024)  -- dominant GEMM
    gemm_kernel<0, false><<<dim3((Vv + 127) / 128, 1), 256>>>(logit_in, W_logit, b_logit, logit, Bb, Vv, Hh, 0);
    // 15) scatter-max masked energies into extended vocab
    scatter_kernel<<<Bb, Ss>>>(energy, ext_x, scat);
    // 16) combine into final out_logit
    combine_kernel<<<(Bb * VE + 255) / 256, 256>>>(logit, scat, out);
}

// round 3
// speedup vs baseline: 2.3135x; 2.3135x over previous
#include <cuda_runtime.h>
#include <math.h>

#define Bb 64
#define Ss 400
#define Hh 1024
#define Ee 300
#define Vv 50000
#define NOOV 50
#define VE 50050
#define NEGINF (-1e12f)

typedef unsigned long long ull;

// ---------------- scratch ----------------
__device__ float    g_pooled_raw[Bb*Hh];
__device__ float    g_pooled_feat[Bb*Hh];
__device__ float    g_catA1[Bb*1624];
__device__ float    g_combined[Bb*Ee];
__device__ float    g_catA2[Bb*1324];
__device__ float    g_x[Bb*Ee];
__device__ float    g_gates[Bb*4*Hh];
__device__ float    g_h[Bb*Hh];
__device__ float    g_gvec[Bb*Hh];
__device__ float    g_energy[Bb*Ss];
__device__ float    g_wsum[Bb*Hh];
__device__ float    g_context[Bb*Hh];
__device__ float    g_catHC[Bb*2*Hh];
__device__ float    g_logit_in[Bb*Hh];
__device__ unsigned g_scat[(size_t)Bb*VE];

// ---------------- helpers ----------------
__device__ __forceinline__ unsigned fenc(float f) {
    unsigned u = __float_as_uint(f);
    return (u & 0x80000000u) ? ~u : (u | 0x80000000u);
}
__device__ __forceinline__ float fdec(unsigned u) {
    return (u & 0x80000000u) ? __uint_as_float(u & 0x7fffffffu) : __uint_as_float(~u);
}
__device__ __forceinline__ float sigmf(float x) { return 1.f / (1.f + expf(-x)); }

__device__ __forceinline__ void ffma2(ull& d, ull a, ull b) {
    asm("fma.rn.f32x2 %0, %1, %2, %0;" : "+l"(d) : "l"(a), "l"(b));
}
__device__ __forceinline__ ull dup2(float x) {
    ull d; asm("mov.b64 %0, {%1, %1};" : "=l"(d) : "f"(x)); return d;
}
__device__ __forceinline__ void unpack2(ull v, float& lo, float& hi) {
    asm("mov.b64 {%0, %1}, %2;" : "=f"(lo), "=f"(hi) : "l"(v));
}

// ---------------- bias init: C[m,n] = b1[n] + b2[n] (nullable) ----------------
__global__ void bias_init_kernel(float* __restrict__ C, const float* __restrict__ b1,
                                 const float* __restrict__ b2, int M, int N)
{
    int i = blockIdx.x * 256 + threadIdx.x;
    if (i >= M * N) return;
    int n = i % N;
    float v = 0.f;
    if (b1) v += b1[n];
    if (b2) v += b2[n];
    C[i] = v;
}

// ---------------- split-K skinny GEMM (M=64), FFMA2, atomic accumulate ----------------
// C[64,N] += A[64,K] @ B  ; B row-major (K,N) or TRANSB (N,K)
template<bool TRANSB>
__global__ __launch_bounds__(128)
void gemm_splitk_kernel(const float* __restrict__ A, const float* __restrict__ Bm,
                        float* __restrict__ C, int N, int K, int KC)
{
    __shared__ float As[16][64];
    __shared__ float Bs[16][128];
    const int tid = threadIdx.x;          // 128
    const int tx = tid & 15, ty = tid >> 4;
    const int n0 = blockIdx.x * 128;
    const int kc0 = blockIdx.y * KC;
    const int kend = min(kc0 + KC, K);

    ull acc[8][4];
#pragma unroll
    for (int i = 0; i < 8; i++)
#pragma unroll
        for (int j = 0; j < 4; j++) acc[i][j] = 0ull;

    for (int k0 = kc0; k0 < kend; k0 += 16) {
        // A tile: 64 x 16
#pragma unroll
        for (int j = 0; j < 8; j++) {
            int i = tid + j * 128;
            int m = i >> 4, kk = i & 15;
            As[kk][m] = (k0 + kk < kend) ? A[(size_t)m * K + k0 + kk] : 0.f;
        }
        // B tile: 16 x 128
#pragma unroll
        for (int j = 0; j < 16; j++) {
            int i = tid + j * 128;
            if (TRANSB) {
                int n = i >> 4, kk = i & 15;
                Bs[kk][n] = (k0 + kk < kend && n0 + n < N) ? Bm[(size_t)(n0 + n) * K + k0 + kk] : 0.f;
            } else {
                int kk = i >> 7, n = i & 127;
                Bs[kk][n] = (k0 + kk < kend && n0 + n < N) ? Bm[(size_t)(k0 + kk) * N + n0 + n] : 0.f;
            }
        }
        __syncthreads();

#pragma unroll
        for (int kk = 0; kk < 16; kk++) {
            float4 av0 = *reinterpret_cast<const float4*>(&As[kk][ty * 8]);
            float4 av1 = *reinterpret_cast<const float4*>(&As[kk][ty * 8 + 4]);
            ull ad[8];
            ad[0] = dup2(av0.x); ad[1] = dup2(av0.y); ad[2] = dup2(av0.z); ad[3] = dup2(av0.w);
            ad[4] = dup2(av1.x); ad[5] = dup2(av1.y); ad[6] = dup2(av1.z); ad[7] = dup2(av1.w);
            ulonglong2 b01 = *reinterpret_cast<const ulonglong2*>(&Bs[kk][tx * 8]);
            ulonglong2 b23 = *reinterpret_cast<const ulonglong2*>(&Bs[kk][tx * 8 + 4]);
            ull bp[4] = {b01.x, b01.y, b23.x, b23.y};
#pragma unroll
            for (int i = 0; i < 8; i++)
#pragma unroll
                for (int j = 0; j < 4; j++) ffma2(acc[i][j], ad[i], bp[j]);
        }
        __syncthreads();
    }

#pragma unroll
    for (int i = 0; i < 8; i++) {
        int m = ty * 8 + i;
#pragma unroll
        for (int j = 0; j < 4; j++) {
            float lo, hi;
            unpack2(acc[i][j], lo, hi);
            int n = n0 + tx * 8 + 2 * j;
            if (n < N)     atomicAdd(&C[(size_t)m * N + n], lo);
            if (n + 1 < N) atomicAdd(&C[(size_t)m * N + n + 1], hi);
        }
    }
}

// ---------------- big logit GEMM, FFMA2, fused pointer-gen combine epilogue ----------------
// out[m, n] = combine( A[64,1024] @ W[1024,50000] + bias , scat )
__global__ __launch_bounds__(128)
void logit_gemm_kernel(const float* __restrict__ A, const float* __restrict__ W,
                       const float* __restrict__ bias, const unsigned* __restrict__ scat,
                       float* __restrict__ out)
{
    __shared__ float As[16][64];
    __shared__ float Bs[16][128];
    const int tid = threadIdx.x;          // 128
    const int tx = tid & 15, ty = tid >> 4;
    const int n0 = blockIdx.x * 128;

    ull acc[8][4];
#pragma unroll
    for (int i = 0; i < 8; i++)
#pragma unroll
        for (int j = 0; j < 4; j++) acc[i][j] = 0ull;

    // per-thread load coordinates
    const int am = (tid + 0) >> 2;          // A: i = tid + j*128, j<2
    const int ak = (tid & 3) << 2;
    const int am2 = (tid + 128) >> 2;
    // B: i = tid + j*128, j<4: kk = i>>5, nq = (i&31)<<2
    float4 aR0, aR1, bR[4];

    // prefetch tile 0
    {
        aR0 = *reinterpret_cast<const float4*>(&A[(size_t)am * 1024 + ak]);
        aR1 = *reinterpret_cast<const float4*>(&A[(size_t)am2 * 1024 + ak]);
#pragma unroll
        for (int j = 0; j < 4; j++) {
            int i = tid + j * 128;
            int kk = i >> 5, nq = (i & 31) << 2;
            int n = n0 + nq;
            bR[j] = (n < Vv) ? *reinterpret_cast<const float4*>(&W[(size_t)kk * Vv + n])
                             : make_float4(0.f, 0.f, 0.f, 0.f);
        }
    }
    // store tile 0
    As[ak + 0][am] = aR0.x; As[ak + 1][am] = aR0.y; As[ak + 2][am] = aR0.z; As[ak + 3][am] = aR0.w;
    As[ak + 0][am2] = aR1.x; As[ak + 1][am2] = aR1.y; As[ak + 2][am2] = aR1.z; As[ak + 3][am2] = aR1.w;
#pragma unroll
    for (int j = 0; j < 4; j++) {
        int i = tid + j * 128;
        int kk = i >> 5, nq = (i & 31) << 2;
        *reinterpret_cast<float4*>(&Bs[kk][nq]) = bR[j];
    }
    __syncthreads();

    for (int t = 0; t < 64; t++) {
        if (t < 63) {
            int k0 = (t + 1) * 16;
            aR0 = *reinterpret_cast<const float4*>(&A[(size_t)am * 1024 + k0 + ak]);
            aR1 = *reinterpret_cast<const float4*>(&A[(size_t)am2 * 1024 + k0 + ak]);
#pragma unroll
            for (int j = 0; j < 4; j++) {
                int i = tid + j * 128;
                int kk = i >> 5, nq = (i & 31) << 2;
                int n = n0 + nq;
                bR[j] = (n < Vv) ? *reinterpret_cast<const float4*>(&W[(size_t)(k0 + kk) * Vv + n])
                                 : make_float4(0.f, 0.f, 0.f, 0.f);
            }
        }
#pragma unroll
        for (int kk = 0; kk < 16; kk++) {
            float4 av0 = *reinterpret_cast<const float4*>(&As[kk][ty * 8]);
            float4 av1 = *reinterpret_cast<const float4*>(&As[kk][ty * 8 + 4]);
            ull ad[8];
            ad[0] = dup2(av0.x); ad[1] = dup2(av0.y); ad[2] = dup2(av0.z); ad[3] = dup2(av0.w);
            ad[4] = dup2(av1.x); ad[5] = dup2(av1.y); ad[6] = dup2(av1.z); ad[7] = dup2(av1.w);
            ulonglong2 b01 = *reinterpret_cast<const ulonglong2*>(&Bs[kk][tx * 8]);
            ulonglong2 b23 = *reinterpret_cast<const ulonglong2*>(&Bs[kk][tx * 8 + 4]);
            ull bp[4] = {b01.x, b01.y, b23.x, b23.y};
#pragma unroll
            for (int i = 0; i < 8; i++)
#pragma unroll
                for (int j = 0; j < 4; j++) ffma2(acc[i][j], ad[i], bp[j]);
        }
        if (t < 63) {
            __syncthreads();
            As[ak + 0][am] = aR0.x; As[ak + 1][am] = aR0.y; As[ak + 2][am] = aR0.z; As[ak + 3][am] = aR0.w;
            As[ak + 0][am2] = aR1.x; As[ak + 1][am2] = aR1.y; As[ak + 2][am2] = aR1.z; As[ak + 3][am2] = aR1.w;
#pragma unroll
            for (int j = 0; j < 4; j++) {
                int i = tid + j * 128;
                int kk = i >> 5, nq = (i & 31) << 2;
                *reinterpret_cast<float4*>(&Bs[kk][nq]) = bR[j];
            }
            __syncthreads();
        }
    }

    // fused combine epilogue
#pragma unroll
    for (int i = 0; i < 8; i++) {
        int m = ty * 8 + i;
#pragma unroll
        for (int j = 0; j < 4; j++) {
            float v2[2];
            unpack2(acc[i][j], v2[0], v2[1]);
#pragma unroll
            for (int c = 0; c < 2; c++) {
                int n = n0 + tx * 8 + 2 * j + c;
                if (n >= Vv) continue;
                float v = v2[c] + bias[n];
                float sc = fdec(scat[(size_t)m * VE + n]);
                if (sc == NEGINF) sc = 0.f;
                float o = v + sc;
                if (o == NEGINF) o = 0.f;
                if (n == 1) o = NEGINF;   // UNK_ID
                out[(size_t)m * VE + n] = o;
            }
        }
    }
}

// OOV tail: columns [V, V+50)
__global__ void oov_kernel(const unsigned* __restrict__ scat, float* __restrict__ out)
{
    int i = blockIdx.x * 256 + threadIdx.x;
    if (i >= Bb * NOOV) return;
    int b = i / NOOV, v = Vv + i % NOOV;
    float sc = fdec(scat[(size_t)b * VE + v]);
    if (sc == NEGINF) sc = 0.f;
    float o = sc;
    if (o == NEGINF) o = 0.f;
    out[(size_t)b * VE + v] = o;
}

// ---------------- pool ----------------
__global__ void pool_kernel(const float* __restrict__ enc, float* __restrict__ out)
{
    int b = blockIdx.y;
    int h = blockIdx.x * 256 + threadIdx.x;
    const float* p = enc + (size_t)b * Ss * Hh + h;
    float a0 = 0.f, a1 = 0.f, a2 = 0.f, a3 = 0.f;
    for (int s = 0; s < Ss; s += 4) {
        a0 += p[(size_t)(s + 0) * Hh];
        a1 += p[(size_t)(s + 1) * Hh];
        a2 += p[(size_t)(s + 2) * Hh];
        a3 += p[(size_t)(s + 3) * Hh];
    }
    out[b * Hh + h] = (a0 + a1 + a2 + a3) * (1.0f / Ss);
}

// ---------------- pack kernels ----------------
__global__ void pack1_kernel(const int* __restrict__ y, const float* __restrict__ emb,
                             const float* __restrict__ pooled, const float* __restrict__ dec,
                             float* __restrict__ out)
{
    int b = blockIdx.x;
    int yy = y[b];
    for (int i = threadIdx.x; i < 1624; i += blockDim.x) {
        float v;
        if (i < Ee)           v = emb[(size_t)yy * Ee + i];
        else if (i < Ee + Hh) v = pooled[b * Hh + (i - Ee)];
        else                  v = dec[b * Ee + (i - Ee - Hh)];
        out[b * 1624 + i] = v;
    }
}

__global__ void pack2_kernel(const float* __restrict__ comb, const float* __restrict__ pctx,
                             float* __restrict__ out)
{
    int b = blockIdx.x;
    for (int i = threadIdx.x; i < 1324; i += blockDim.x)
        out[b * 1324 + i] = (i < Ee) ? comb[b * Ee + i] : pctx[b * Hh + (i - Ee)];
}

__global__ void pack3_kernel(const float* __restrict__ h, const float* __restrict__ ctx,
                             float* __restrict__ out, float* __restrict__ dctx)
{
    int b = blockIdx.x;
    for (int i = threadIdx.x; i < 2 * Hh; i += blockDim.x) {
        float v = (i < Hh) ? h[b * Hh + i] : ctx[b * Hh + (i - Hh)];
        out[b * 2 * Hh + i] = v;
        if (i >= Hh) dctx[b * Hh + (i - Hh)] = v;
    }
}

// ---------------- LSTM pointwise ----------------
__global__ void lstm_kernel(const float* __restrict__ gates, const float* __restrict__ c0,
                            float* __restrict__ hs, float* __restrict__ dh, float* __restrict__ dc)
{
    int idx = blockIdx.x * 256 + threadIdx.x;
    if (idx >= Bb * Hh) return;
    int b = idx >> 10, j = idx & (Hh - 1);
    const float* gb = gates + (size_t)b * 4 * Hh;
    float gi = gb[j], gf = gb[Hh + j], gg = gb[2 * Hh + j], go = gb[3 * Hh + j];
    float c = sigmf(gf) * c0[idx] + sigmf(gi) * tanhf(gg);
    float h = sigmf(go) * tanhf(c);
    hs[idx] = h; dh[idx] = h; dc[idx] = c;
}

// ---------------- tanh in place ----------------
__global__ void tanh_kernel(float* __restrict__ C, int n)
{
    int i = blockIdx.x * 256 + threadIdx.x;
    if (i < n) C[i] = tanhf(C[i]);
}

// ---------------- fused attention per batch row ----------------
__global__ void attention_kernel(const float* __restrict__ enc, const float* __restrict__ gv,
                                 const float* __restrict__ hv, const float* __restrict__ benc,
                                 const unsigned int* __restrict__ mask,
                                 float* __restrict__ energy_out, float* __restrict__ wsum)
{
    int b = blockIdx.x;
    int tid = threadIdx.x;                 // 512 threads
    int warp = tid >> 5, lane = tid & 31;
    __shared__ float gsh[Hh];
    __shared__ float esh[Ss];
    __shared__ float red[16];
    __shared__ float sh_hb, sh_mx, sh_sum;

    gsh[tid]       = gv[b * Hh + tid];
    gsh[tid + 512] = gv[b * Hh + tid + 512];

    float p = hv[b * Hh + tid] * benc[tid] + hv[b * Hh + tid + 512] * benc[tid + 512];
    for (int o = 16; o; o >>= 1) p += __shfl_xor_sync(0xffffffffu, p, o);
    if (lane == 0) red[warp] = p;
    __syncthreads();
    if (warp == 0) {
        float v = (lane < 16) ? red[lane] : 0.f;
        for (int o = 8; o; o >>= 1) v += __shfl_xor_sync(0xffffffffu, v, o);
        if (lane == 0) sh_hb = v;
    }
    __syncthreads();
    float hb = sh_hb;

    const float* eb = enc + (size_t)b * Ss * Hh;
    for (int s = warp; s < Ss; s += 16) {
        const float* row = eb + (size_t)s * Hh;
        float acc = 0.f;
#pragma unroll 8
        for (int i = lane; i < Hh; i += 32) acc += row[i] * gsh[i];
        for (int o = 16; o; o >>= 1) acc += __shfl_xor_sync(0xffffffffu, acc, o);
        if (lane == 0) {
            float e = (mask[b * Ss + s] != 0u) ? NEGINF : (acc + hb);
            esh[s] = e;
            energy_out[b * Ss + s] = e;
        }
    }
    __syncthreads();

    float m = (tid < Ss) ? esh[tid] : -3.4e38f;
    for (int o = 16; o; o >>= 1) m = fmaxf(m, __shfl_xor_sync(0xffffffffu, m, o));
    if (lane == 0) red[warp] = m;
    __syncthreads();
    if (warp == 0) {
        float v = (lane < 16) ? red[lane] : -3.4e38f;
        for (int o = 8; o; o >>= 1) v = fmaxf(v, __shfl_xor_sync(0xffffffffu, v, o));
        if (lane == 0) sh_mx = v;
    }
    __syncthreads();
    float mx = sh_mx;

    float sm = 0.f;
    if (tid < Ss) { float pe = expf(esh[tid] - mx); esh[tid] = pe; sm = pe; }
    __syncthreads();
    for (int o = 16; o; o >>= 1) sm += __shfl_xor_sync(0xffffffffu, sm, o);
    if (lane == 0) red[warp] = sm;
    __syncthreads();
    if (warp == 0) {
        float v = (lane < 16) ? red[lane] : 0.f;
        for (int o = 8; o; o >>= 1) v += __shfl_xor_sync(0xffffffffu, v, o);
        if (lane == 0) sh_sum = v;
    }
    __syncthreads();
    float inv = 1.f / sh_sum;

    float a0 = 0.f, a1 = 0.f;
    for (int s = 0; s < Ss; s++) {
        float a = esh[s];
        a0 += a * eb[(size_t)s * Hh + tid];
        a1 += a * eb[(size_t)s * Hh + tid + 512];
    }
    wsum[b * Hh + tid]       = a0 * inv;
    wsum[b * Hh + tid + 512] = a1 * inv;
}

// ---------------- scatter-max ----------------
__global__ void init_scat_kernel(unsigned* __restrict__ scat)
{
    size_t idx = (size_t)blockIdx.x * 256 + threadIdx.x;
    if (idx < (size_t)Bb * VE) scat[idx] = fenc(NEGINF);
}

__global__ void scatter_kernel(const float* __restrict__ energy, const int* __restrict__ ext_x,
                               unsigned* __restrict__ scat)
{
    int b = blockIdx.x;
    int s = threadIdx.x;
    if (s < Ss) {
        float e = energy[b * Ss + s];
        int tok = ext_x[b * Ss + s];
        atomicMax(&scat[(size_t)b * VE + tok], fenc(e));
    }
}

// ---------------- host ----------------
extern "C" void kernel_launch(void* const* d_in, const int* in_sizes, int n_in,
                              void* d_out, int out_size)
{
    const int*   y        = (const int*)d_in[0];
    const int*   ext_x    = (const int*)d_in[1];
    const float* prev_h   = (const float*)d_in[2];
    const float* prev_c   = (const float*)d_in[3];
    const float* prev_ctx = (const float*)d_in[4];
    const float* enc      = (const float*)d_in[5];
    const unsigned int* mask = (const unsigned int*)d_in[6];
    const float* dec_out  = (const float*)d_in[7];
    const float* emb      = (const float*)d_in[8];
    const float* W_enc    = (const float*)d_in[9];
    const float* b_enc    = (const float*)d_in[10];
    const float* W_comb   = (const float*)d_in[11];
    const float* b_comb   = (const float*)d_in[12];
    const float* W_red    = (const float*)d_in[13];
    const float* b_red    = (const float*)d_in[14];
    const float* W_ih     = (const float*)d_in[15];
    const float* W_hh     = (const float*)d_in[16];
    const float* b_ih     = (const float*)d_in[17];
    const float* b_hh     = (const float*)d_in[18];
    const float* W_cat    = (const float*)d_in[19];
    const float* b_cat    = (const float*)d_in[20];
    const float* W_logit  = (const float*)d_in[21];
    const float* b_logit  = (const float*)d_in[22];
    float* out = (float*)d_out;

    float *pooled_raw, *pooled_feat, *catA1, *combined, *catA2, *xv, *gates, *hs;
    float *gvec, *energy, *wsum, *context, *catHC, *logit_in;
    unsigned* scat;
    cudaGetSymbolAddress((void**)&pooled_raw,  g_pooled_raw);
    cudaGetSymbolAddress((void**)&pooled_feat, g_pooled_feat);
    cudaGetSymbolAddress((void**)&catA1,       g_catA1);
    cudaGetSymbolAddress((void**)&combined,    g_combined);
    cudaGetSymbolAddress((void**)&catA2,       g_catA2);
    cudaGetSymbolAddress((void**)&xv,          g_x);
    cudaGetSymbolAddress((void**)&gates,       g_gates);
    cudaGetSymbolAddress((void**)&hs,          g_h);
    cudaGetSymbolAddress((void**)&gvec,        g_gvec);
    cudaGetSymbolAddress((void**)&energy,      g_energy);
    cudaGetSymbolAddress((void**)&wsum,        g_wsum);
    cudaGetSymbolAddress((void**)&context,     g_context);
    cudaGetSymbolAddress((void**)&catHC,       g_catHC);
    cudaGetSymbolAddress((void**)&logit_in,    g_logit_in);
    cudaGetSymbolAddress((void**)&scat,        g_scat);

    const size_t O1 = (size_t)Bb * VE;
    const size_t O2 = O1 + (size_t)Bb * Hh;
    const size_t O3 = O2 + (size_t)Bb * Hh;

    init_scat_kernel<<<(Bb * VE + 255) / 256, 256>>>(scat);

    // 1) pool encoder outputs
    pool_kernel<<<dim3(Hh / 256, Bb), 256>>>(enc, pooled_raw);
    // 2) pooled_feat = pooled_raw @ W_enc + b_enc
    bias_init_kernel<<<(Bb * Hh + 255) / 256, 256>>>(pooled_feat, b_enc, nullptr, Bb, Hh);
    gemm_splitk_kernel<false><<<dim3(8, 16), 128>>>(pooled_raw, W_enc, pooled_feat, Hh, Hh, 64);
    // 3) catA1
    pack1_kernel<<<Bb, 256>>>(y, emb, pooled_feat, dec_out, catA1);
    // 4) combined = catA1 @ W_comb + b_comb
    bias_init_kernel<<<(Bb * Ee + 255) / 256, 256>>>(combined, b_comb, nullptr, Bb, Ee);
    gemm_splitk_kernel<false><<<dim3(3, 26), 128>>>(catA1, W_comb, combined, Ee, 1624, 64);
    // 5) catA2
    pack2_kernel<<<Bb, 256>>>(combined, prev_ctx, catA2);
    // 6) x = catA2 @ W_red + b_red
    bias_init_kernel<<<(Bb * Ee + 255) / 256, 256>>>(xv, b_red, nullptr, Bb, Ee);
    gemm_splitk_kernel<false><<<dim3(3, 21), 128>>>(catA2, W_red, xv, Ee, 1324, 64);
    // 7) gates = b_ih + b_hh + x@W_ih + h0@W_hh  (both GEMMs atomically accumulate)
    bias_init_kernel<<<(Bb * 4 * Hh + 255) / 256, 256>>>(gates, b_ih, b_hh, Bb, 4 * Hh);
    gemm_splitk_kernel<false><<<dim3(32, 5), 128>>>(xv, W_ih, gates, 4 * Hh, Ee, 64);
    gemm_splitk_kernel<false><<<dim3(32, 16), 128>>>(prev_h, W_hh, gates, 4 * Hh, Hh, 64);
    // 8) LSTM pointwise
    lstm_kernel<<<(Bb * Hh + 255) / 256, 256>>>(gates, prev_c, hs, out + O1, out + O2);
    // 9) gvec = h @ W_enc^T
    bias_init_kernel<<<(Bb * Hh + 255) / 256, 256>>>(gvec, nullptr, nullptr, Bb, Hh);
    gemm_splitk_kernel<true><<<dim3(8, 16), 128>>>(hs, W_enc, gvec, Hh, Hh, 64);
    // 10) attention (energy, softmax, weighted enc sum)
    attention_kernel<<<Bb, 512>>>(enc, gvec, hs, b_enc, mask, energy, wsum);
    // 15) scatter-max energies (early: logit epilogue needs it)
    scatter_kernel<<<Bb, Ss>>>(energy, ext_x, scat);
    // 11) context = wsum @ W_enc + b_enc
    bias_init_kernel<<<(Bb * Hh + 255) / 256, 256>>>(context, b_enc, nullptr, Bb, Hh);
    gemm_splitk_kernel<false><<<dim3(8, 16), 128>>>(wsum, W_enc, context, Hh, Hh, 64);
    // 12) catHC + context output
    pack3_kernel<<<Bb, 256>>>(hs, context, catHC, out + O3);
    // 13) logit_in = tanh(catHC @ W_cat + b_cat)
    bias_init_kernel<<<(Bb * Hh + 255) / 256, 256>>>(logit_in, b_cat, nullptr, Bb, Hh);
    gemm_splitk_kernel<false><<<dim3(8, 32), 128>>>(catHC, W_cat, logit_in, Hh, 2 * Hh, 64);
    tanh_kernel<<<(Bb * Hh + 255) / 256, 256>>>(logit_in, Bb * Hh);
    // 14) logit GEMM + fused combine -> out
    logit_gemm_kernel<<<(Vv + 127) / 128, 128>>>(logit_in, W_logit, b_logit, scat, out);
    // 16) OOV tail
    oov_kernel<<<(Bb * NOOV + 255) / 256, 256>>>(scat, out);
}

// round 4
// speedup vs baseline: 4.0512x; 1.7511x over previous
#include <cuda_runtime.h>
#include <math.h>

#define Bb 64
#define Ss 400
#define Hh 1024
#define Ee 300
#define Vv 50000
#define NOOV 50
#define VE 50050
#define NEGINF (-1e12f)

typedef unsigned long long ull;

// ---------------- scratch ----------------
__device__ float    g_pooled_raw[Bb*Hh];
__device__ float    g_pooled_feat[Bb*Hh];
__device__ float    g_catA1[Bb*1624];
__device__ float    g_combined[Bb*Ee];
__device__ float    g_catA2[Bb*1324];
__device__ float    g_x[Bb*Ee];
__device__ float    g_gates[Bb*4*Hh];
__device__ float    g_h[Bb*Hh];
__device__ float    g_gvec[Bb*Hh];
__device__ float    g_energy[Bb*Ss];
__device__ float    g_attn[Bb*Ss];
__device__ float    g_wsum[Bb*Hh];
__device__ float    g_catHC[Bb*2*Hh];
__device__ float    g_logit_in[Bb*Hh];
__device__ unsigned g_scat[(size_t)Bb*VE];

// ---------------- helpers ----------------
__device__ __forceinline__ unsigned fenc(float f) {
    unsigned u = __float_as_uint(f);
    return (u & 0x80000000u) ? ~u : (u | 0x80000000u);
}
__device__ __forceinline__ float fdec(unsigned u) {
    return (u & 0x80000000u) ? __uint_as_float(u & 0x7fffffffu) : __uint_as_float(~u);
}
__device__ __forceinline__ float sigmf(float x) { return 1.f / (1.f + expf(-x)); }

__device__ __forceinline__ void ffma2(ull& d, ull a, ull b) {
    asm("fma.rn.f32x2 %0, %1, %2, %0;" : "+l"(d) : "l"(a), "l"(b));
}
__device__ __forceinline__ ull dup2(float x) {
    ull d; asm("mov.b64 %0, {%1, %1};" : "=l"(d) : "f"(x)); return d;
}
__device__ __forceinline__ void unpack2(ull v, float& lo, float& hi) {
    asm("mov.b64 {%0, %1}, %2;" : "=f"(lo), "=f"(hi) : "l"(v));
}

// ---------------- init everything up front (one kernel) ----------------
__global__ void init_all_kernel(unsigned* __restrict__ scat,
                                float* __restrict__ pooled_feat, float* __restrict__ combined,
                                float* __restrict__ xv, float* __restrict__ gates,
                                float* __restrict__ gvec, float* __restrict__ catHC,
                                float* __restrict__ logit_in, float* __restrict__ wsum,
                                const float* __restrict__ b_enc, const float* __restrict__ b_comb,
                                const float* __restrict__ b_red, const float* __restrict__ b_ih,
                                const float* __restrict__ b_hh, const float* __restrict__ b_cat)
{
    int i = blockIdx.x * 256 + threadIdx.x;
    const int S0 = Bb * VE;
    if (i < S0) { scat[i] = fenc(NEGINF); return; }
    i -= S0;
    if (i < Bb * Hh) { pooled_feat[i] = b_enc[i & 1023]; return; }
    i -= Bb * Hh;
    if (i < Bb * Ee) { combined[i] = b_comb[i % Ee]; return; }
    i -= Bb * Ee;
    if (i < Bb * Ee) { xv[i] = b_red[i % Ee]; return; }
    i -= Bb * Ee;
    if (i < Bb * 4 * Hh) { int n = i & 4095; gates[i] = b_ih[n] + b_hh[n]; return; }
    i -= Bb * 4 * Hh;
    if (i < Bb * Hh) { gvec[i] = 0.f; return; }
    i -= Bb * Hh;
    if (i < Bb * Hh) { catHC[(size_t)(i >> 10) * 2048 + 1024 + (i & 1023)] = b_enc[i & 1023]; return; }
    i -= Bb * Hh;
    if (i < Bb * Hh) { logit_in[i] = b_cat[i & 1023]; return; }
    i -= Bb * Hh;
    if (i < Bb * Hh) { wsum[i] = 0.f; return; }
}

// ---------------- split-K skinny GEMM v2: prefetched, FFMA2, atomic accumulate ----------------
// C[64, n (stride ldc)] += A[64,K] @ B ; B row-major (K,N) or TRANSB (N,K)
template<bool TRANSB>
__global__ __launch_bounds__(128)
void gemm_splitk2(const float* __restrict__ A, const float* __restrict__ Bm,
                  float* __restrict__ C, int N, int K, int KC, int ldc)
{
    __shared__ float As[16][64];
    __shared__ float Bs[16][128];
    const int tid = threadIdx.x;
    const int tx = tid & 15, ty = tid >> 4;
    const int n0 = blockIdx.x * 128;
    const int kc0 = blockIdx.y * KC;
    const int kend = min(kc0 + KC, K);
    const int ntiles = (kend - kc0 + 15) >> 4;

    const int am = tid >> 2;            // 0..31 (rows am and am+32)
    const int ak = (tid & 3) << 2;
    const int bk = (tid & 3) << 2;      // TRANSB coords
    const int bnb = tid >> 2;

    ull acc[8][4];
#pragma unroll
    for (int i = 0; i < 8; i++)
#pragma unroll
        for (int j = 0; j < 4; j++) acc[i][j] = 0ull;

    float4 aR0, aR1, bR[4];

    auto loadTile = [&](int k0) {
        // --- A ---
        if (k0 + 16 <= kend) {
            aR0 = *reinterpret_cast<const float4*>(&A[(size_t)am * K + k0 + ak]);
            aR1 = *reinterpret_cast<const float4*>(&A[(size_t)(am + 32) * K + k0 + ak]);
        } else {
            float v[4], w[4];
#pragma unroll
            for (int l = 0; l < 4; l++) {
                int k = k0 + ak + l;
                v[l] = (k < kend) ? A[(size_t)am * K + k] : 0.f;
                w[l] = (k < kend) ? A[(size_t)(am + 32) * K + k] : 0.f;
            }
            aR0 = make_float4(v[0], v[1], v[2], v[3]);
            aR1 = make_float4(w[0], w[1], w[2], w[3]);
        }
        // --- B ---
        if (!TRANSB) {
            if (k0 + 16 <= kend && n0 + 128 <= N) {
#pragma unroll
                for (int j = 0; j < 4; j++) {
                    int i = tid + j * 128;
                    int kk = i >> 5, nq = (i & 31) << 2;
                    bR[j] = *reinterpret_cast<const float4*>(&Bm[(size_t)(k0 + kk) * N + n0 + nq]);
                }
            } else {
#pragma unroll
                for (int j = 0; j < 4; j++) {
                    int i = tid + j * 128;
                    int kk = i >> 5, nq = (i & 31) << 2;
                    float v[4];
#pragma unroll
                    for (int l = 0; l < 4; l++) {
                        int k = k0 + kk, n = n0 + nq + l;
                        v[l] = (k < kend && n < N) ? Bm[(size_t)k * N + n] : 0.f;
                    }
                    bR[j] = make_float4(v[0], v[1], v[2], v[3]);
                }
            }
        } else {
            if (k0 + 16 <= kend && n0 + 128 <= N) {
#pragma unroll
                for (int j = 0; j < 4; j++) {
                    int bn = bnb + 32 * j;
                    bR[j] = *reinterpret_cast<const float4*>(&Bm[(size_t)(n0 + bn) * K + k0 + bk]);
                }
            } else {
#pragma unroll
                for (int j = 0; j < 4; j++) {
                    int bn = bnb + 32 * j;
                    float v[4];
#pragma unroll
                    for (int l = 0; l < 4; l++) {
                        int k = k0 + bk + l;
                        v[l] = (n0 + bn < N && k < kend) ? Bm[(size_t)(n0 + bn) * K + k] : 0.f;
                    }
                    bR[j] = make_float4(v[0], v[1], v[2], v[3]);
                }
            }
        }
    };

    auto storeTile = [&]() {
        As[ak + 0][am] = aR0.x; As[ak + 1][am] = aR0.y;
        As[ak + 2][am] = aR0.z; As[ak + 3][am] = aR0.w;
        As[ak + 0][am + 32] = aR1.x; As[ak + 1][am + 32] = aR1.y;
        As[ak + 2][am + 32] = aR1.z; As[ak + 3][am + 32] = aR1.w;
        if (!TRANSB) {
#pragma unroll
            for (int j = 0; j < 4; j++) {
                int i = tid + j * 128;
                int kk = i >> 5, nq = (i & 31) << 2;
                *reinterpret_cast<float4*>(&Bs[kk][nq]) = bR[j];
            }
        } else {
#pragma unroll
            for (int j = 0; j < 4; j++) {
                int bn = bnb + 32 * j;
                Bs[bk + 0][bn] = bR[j].x; Bs[bk + 1][bn] = bR[j].y;
                Bs[bk + 2][bn] = bR[j].z; Bs[bk + 3][bn] = bR[j].w;
            }
        }
    };

    loadTile(kc0);
    storeTile();
    __syncthreads();

    for (int t = 0; t < ntiles; t++) {
        if (t + 1 < ntiles) loadTile(kc0 + (t + 1) * 16);
#pragma unroll
        for (int kk = 0; kk < 16; kk++) {
            float4 av0 = *reinterpret_cast<const float4*>(&As[kk][ty * 8]);
            float4 av1 = *reinterpret_cast<const float4*>(&As[kk][ty * 8 + 4]);
            ull ad[8];
            ad[0] = dup2(av0.x); ad[1] = dup2(av0.y); ad[2] = dup2(av0.z); ad[3] = dup2(av0.w);
            ad[4] = dup2(av1.x); ad[5] = dup2(av1.y); ad[6] = dup2(av1.z); ad[7] = dup2(av1.w);
            ulonglong2 b01 = *reinterpret_cast<const ulonglong2*>(&Bs[kk][tx * 8]);
            ulonglong2 b23 = *reinterpret_cast<const ulonglong2*>(&Bs[kk][tx * 8 + 4]);
            ull bp[4] = {b01.x, b01.y, b23.x, b23.y};
#pragma unroll
            for (int i = 0; i < 8; i++)
#pragma unroll
                for (int j = 0; j < 4; j++) ffma2(acc[i][j], ad[i], bp[j]);
        }
        if (t + 1 < ntiles) {
            __syncthreads();
            storeTile();
            __syncthreads();
        }
    }

#pragma unroll
    for (int i = 0; i < 8; i++) {
        int m = ty * 8 + i;
#pragma unroll
        for (int j = 0; j < 4; j++) {
            float lo, hi;
            unpack2(acc[i][j], lo, hi);
            int n = n0 + tx * 8 + 2 * j;
            if (n < N)     atomicAdd(&C[(size_t)m * ldc + n], lo);
            if (n + 1 < N) atomicAdd(&C[(size_t)m * ldc + n + 1], hi);
        }
    }
}

// ---------------- big logit GEMM, FFMA2, fused pointer-gen combine epilogue ----------------
__global__ __launch_bounds__(128)
void logit_gemm_kernel(const float* __restrict__ A, const float* __restrict__ W,
                       const float* __restrict__ bias, const unsigned* __restrict__ scat,
                       float* __restrict__ out)
{
    __shared__ float As[16][64];
    __shared__ float Bs[16][128];
    const int tid = threadIdx.x;
    const int tx = tid & 15, ty = tid >> 4;
    const int n0 = blockIdx.x * 128;

    ull acc[8][4];
#pragma unroll
    for (int i = 0; i < 8; i++)
#pragma unroll
        for (int j = 0; j < 4; j++) acc[i][j] = 0ull;

    const int am = tid >> 2;
    const int ak = (tid & 3) << 2;
    const int am2 = am + 32;
    float4 aR0, aR1, bR[4];

    aR0 = *reinterpret_cast<const float4*>(&A[(size_t)am * 1024 + ak]);
    aR1 = *reinterpret_cast<const float4*>(&A[(size_t)am2 * 1024 + ak]);
#pragma unroll
    for (int j = 0; j < 4; j++) {
        int i = tid + j * 128;
        int kk = i >> 5, nq = (i & 31) << 2;
        int n = n0 + nq;
        bR[j] = (n < Vv) ? *reinterpret_cast<const float4*>(&W[(size_t)kk * Vv + n])
                         : make_float4(0.f, 0.f, 0.f, 0.f);
    }
    As[ak + 0][am] = aR0.x; As[ak + 1][am] = aR0.y; As[ak + 2][am] = aR0.z; As[ak + 3][am] = aR0.w;
    As[ak + 0][am2] = aR1.x; As[ak + 1][am2] = aR1.y; As[ak + 2][am2] = aR1.z; As[ak + 3][am2] = aR1.w;
#pragma unroll
    for (int j = 0; j < 4; j++) {
        int i = tid + j * 128;
        int kk = i >> 5, nq = (i & 31) << 2;
        *reinterpret_cast<float4*>(&Bs[kk][nq]) = bR[j];
    }
    __syncthreads();

    for (int t = 0; t < 64; t++) {
        if (t < 63) {
            int k0 = (t + 1) * 16;
            aR0 = *reinterpret_cast<const float4*>(&A[(size_t)am * 1024 + k0 + ak]);
            aR1 = *reinterpret_cast<const float4*>(&A[(size_t)am2 * 1024 + k0 + ak]);
#pragma unroll
            for (int j = 0; j < 4; j++) {
                int i = tid + j * 128;
                int kk = i >> 5, nq = (i & 31) << 2;
                int n = n0 + nq;
                bR[j] = (n < Vv) ? *reinterpret_cast<const float4*>(&W[(size_t)(k0 + kk) * Vv + n])
                                 : make_float4(0.f, 0.f, 0.f, 0.f);
            }
        }
#pragma unroll
        for (int kk = 0; kk < 16; kk++) {
            float4 av0 = *reinterpret_cast<const float4*>(&As[kk][ty * 8]);
            float4 av1 = *reinterpret_cast<const float4*>(&As[kk][ty * 8 + 4]);
            ull ad[8];
            ad[0] = dup2(av0.x); ad[1] = dup2(av0.y); ad[2] = dup2(av0.z); ad[3] = dup2(av0.w);
            ad[4] = dup2(av1.x); ad[5] = dup2(av1.y); ad[6] = dup2(av1.z); ad[7] = dup2(av1.w);
            ulonglong2 b01 = *reinterpret_cast<const ulonglong2*>(&Bs[kk][tx * 8]);
            ulonglong2 b23 = *reinterpret_cast<const ulonglong2*>(&Bs[kk][tx * 8 + 4]);
            ull bp[4] = {b01.x, b01.y, b23.x, b23.y};
#pragma unroll
            for (int i = 0; i < 8; i++)
#pragma unroll
                for (int j = 0; j < 4; j++) ffma2(acc[i][j], ad[i], bp[j]);
        }
        if (t < 63) {
            __syncthreads();
            As[ak + 0][am] = aR0.x; As[ak + 1][am] = aR0.y; As[ak + 2][am] = aR0.z; As[ak + 3][am] = aR0.w;
            As[ak + 0][am2] = aR1.x; As[ak + 1][am2] = aR1.y; As[ak + 2][am2] = aR1.z; As[ak + 3][am2] = aR1.w;
#pragma unroll
            for (int j = 0; j < 4; j++) {
                int i = tid + j * 128;
                int kk = i >> 5, nq = (i & 31) << 2;
                *reinterpret_cast<float4*>(&Bs[kk][nq]) = bR[j];
            }
            __syncthreads();
        }
    }

#pragma unroll
    for (int i = 0; i < 8; i++) {
        int m = ty * 8 + i;
#pragma unroll
        for (int j = 0; j < 4; j++) {
            float v2[2];
            unpack2(acc[i][j], v2[0], v2[1]);
#pragma unroll
            for (int c = 0; c < 2; c++) {
                int n = n0 + tx * 8 + 2 * j + c;
                if (n >= Vv) continue;
                float v = v2[c] + bias[n];
                float sc = fdec(scat[(size_t)m * VE + n]);
                if (sc == NEGINF) sc = 0.f;
                float o = v + sc;
                if (o == NEGINF) o = 0.f;
                if (n == 1) o = NEGINF;
                out[(size_t)m * VE + n] = o;
            }
        }
    }
}

__global__ void oov_kernel(const unsigned* __restrict__ scat, float* __restrict__ out)
{
    int i = blockIdx.x * 256 + threadIdx.x;
    if (i >= Bb * NOOV) return;
    int b = i / NOOV, v = Vv + i % NOOV;
    float sc = fdec(scat[(size_t)b * VE + v]);
    if (sc == NEGINF) sc = 0.f;
    float o = sc;
    if (o == NEGINF) o = 0.f;
    out[(size_t)b * VE + v] = o;
}

// ---------------- pool ----------------
__global__ void pool_kernel(const float* __restrict__ enc, float* __restrict__ out)
{
    int b = blockIdx.y;
    int h = blockIdx.x * 256 + threadIdx.x;
    const float* p = enc + (size_t)b * Ss * Hh + h;
    float a0 = 0.f, a1 = 0.f, a2 = 0.f, a3 = 0.f;
    for (int s = 0; s < Ss; s += 4) {
        a0 += p[(size_t)(s + 0) * Hh];
        a1 += p[(size_t)(s + 1) * Hh];
        a2 += p[(size_t)(s + 2) * Hh];
        a3 += p[(size_t)(s + 3) * Hh];
    }
    out[b * Hh + h] = (a0 + a1 + a2 + a3) * (1.0f / Ss);
}

// ---------------- pack kernels ----------------
__global__ void pack1_kernel(const int* __restrict__ y, const float* __restrict__ emb,
                             const float* __restrict__ pooled, const float* __restrict__ dec,
                             float* __restrict__ out)
{
    int b = blockIdx.x;
    int yy = y[b];
    for (int i = threadIdx.x; i < 1624; i += blockDim.x) {
        float v;
        if (i < Ee)           v = emb[(size_t)yy * Ee + i];
        else if (i < Ee + Hh) v = pooled[b * Hh + (i - Ee)];
        else                  v = dec[b * Ee + (i - Ee - Hh)];
        out[b * 1624 + i] = v;
    }
}

__global__ void pack2_kernel(const float* __restrict__ comb, const float* __restrict__ pctx,
                             float* __restrict__ out)
{
    int b = blockIdx.x;
    for (int i = threadIdx.x; i < 1324; i += blockDim.x)
        out[b * 1324 + i] = (i < Ee) ? comb[b * Ee + i] : pctx[b * Hh + (i - Ee)];
}

// ---------------- LSTM pointwise (also fills catHC left half) ----------------
__global__ void lstm_kernel(const float* __restrict__ gates, const float* __restrict__ c0,
                            float* __restrict__ hs, float* __restrict__ dh, float* __restrict__ dc,
                            float* __restrict__ catHC)
{
    int idx = blockIdx.x * 256 + threadIdx.x;
    if (idx >= Bb * Hh) return;
    int b = idx >> 10, j = idx & (Hh - 1);
    const float* gb = gates + (size_t)b * 4 * Hh;
    float gi = gb[j], gf = gb[Hh + j], gg = gb[2 * Hh + j], go = gb[3 * Hh + j];
    float c = sigmf(gf) * c0[idx] + sigmf(gi) * tanhf(gg);
    float h = sigmf(go) * tanhf(c);
    hs[idx] = h; dh[idx] = h; dc[idx] = c;
    catHC[(size_t)b * 2048 + j] = h;
}

// ---------------- tanh(logit_in) + context -> d_out ----------------
__global__ void tanh_ctx_kernel(float* __restrict__ li, const float* __restrict__ catHC,
                                float* __restrict__ out_ctx)
{
    int i = blockIdx.x * 256 + threadIdx.x;
    if (i >= Bb * Hh) return;
    li[i] = tanhf(li[i]);
    out_ctx[i] = catHC[(size_t)(i >> 10) * 2048 + 1024 + (i & 1023)];
}

// ---------------- attention: phase 1, energies (grid: 13 x 64) ----------------
__global__ __launch_bounds__(256)
void energy_kernel(const float* __restrict__ enc, const float* __restrict__ gv,
                   const float* __restrict__ hv, const float* __restrict__ benc,
                   const unsigned int* __restrict__ mask, float* __restrict__ energy)
{
    int b = blockIdx.y, chunk = blockIdx.x;
    int tid = threadIdx.x, warp = tid >> 5, lane = tid & 31;
    __shared__ float gsh[Hh];
    __shared__ float red[8];
    __shared__ float sh_hb;

    // load gvec row
    *reinterpret_cast<float4*>(&gsh[tid * 4]) =
        *reinterpret_cast<const float4*>(&gv[b * Hh + tid * 4]);

    // hb = dot(h[b], b_enc)
    float p = 0.f;
#pragma unroll
    for (int j = 0; j < 4; j++) {
        int i = tid + 256 * j;
        p += hv[b * Hh + i] * benc[i];
    }
    for (int o = 16; o; o >>= 1) p += __shfl_xor_sync(0xffffffffu, p, o);
    if (lane == 0) red[warp] = p;
    __syncthreads();
    if (tid == 0) {
        float v = 0.f;
#pragma unroll
        for (int w = 0; w < 8; w++) v += red[w];
        sh_hb = v;
    }
    __syncthreads();
    float hb = sh_hb;

    const float* eb = enc + (size_t)b * Ss * Hh;
#pragma unroll
    for (int it = 0; it < 4; it++) {
        int s = chunk * 32 + it * 8 + warp;
        if (s >= Ss) break;
        const float* row = eb + (size_t)s * Hh;
        float acc = 0.f;
#pragma unroll 8
        for (int i = lane; i < Hh; i += 32) acc += row[i] * gsh[i];
        for (int o = 16; o; o >>= 1) acc += __shfl_xor_sync(0xffffffffu, acc, o);
        if (lane == 0)
            energy[b * Ss + s] = (mask[b * Ss + s] != 0u) ? NEGINF : (acc + hb);
    }
}

// ---------------- attention: phase 2, softmax -> attn (grid: 64) ----------------
__global__ __launch_bounds__(512)
void softmax_kernel(const float* __restrict__ energy, float* __restrict__ attn)
{
    int b = blockIdx.x;
    int tid = threadIdx.x, warp = tid >> 5, lane = tid & 31;
    __shared__ float esh[Ss];
    __shared__ float red[16];
    __shared__ float sh_mx, sh_sum;

    float e = (tid < Ss) ? energy[b * Ss + tid] : -3.4e38f;
    if (tid < Ss) esh[tid] = e;

    float m = e;
    for (int o = 16; o; o >>= 1) m = fmaxf(m, __shfl_xor_sync(0xffffffffu, m, o));
    if (lane == 0) red[warp] = m;
    __syncthreads();
    if (warp == 0) {
        float v = (lane < 16) ? red[lane] : -3.4e38f;
        for (int o = 8; o; o >>= 1) v = fmaxf(v, __shfl_xor_sync(0xffffffffu, v, o));
        if (lane == 0) sh_mx = v;
    }
    __syncthreads();
    float mx = sh_mx;

    float pe = 0.f;
    if (tid < Ss) pe = expf(esh[tid] - mx);
    float sm = pe;
    for (int o = 16; o; o >>= 1) sm += __shfl_xor_sync(0xffffffffu, sm, o);
    if (lane == 0) red[warp] = sm;
    __syncthreads();
    if (warp == 0) {
        float v = (lane < 16) ? red[lane] : 0.f;
        for (int o = 8; o; o >>= 1) v += __shfl_xor_sync(0xffffffffu, v, o);
        if (lane == 0) sh_sum = v;
    }
    __syncthreads();
    if (tid < Ss) attn[b * Ss + tid] = pe / sh_sum;
}

// ---------------- attention: phase 3, wsum accumulation (grid: 13 x 64) ----------------
__global__ __launch_bounds__(256)
void wsum_kernel(const float* __restrict__ enc, const float* __restrict__ attn,
                 float* __restrict__ wsum)
{
    int b = blockIdx.y, chunk = blockIdx.x;
    int tid = threadIdx.x;
    int s0 = chunk * 32;
    int ns = min(32, Ss - s0);
    __shared__ float ash[32];
    if (tid < 32) ash[tid] = (tid < ns) ? attn[b * Ss + s0 + tid] : 0.f;
    __syncthreads();

    const float* eb = enc + (size_t)b * Ss * Hh + (size_t)s0 * Hh;
    float a0 = 0.f, a1 = 0.f, a2 = 0.f, a3 = 0.f;
    for (int s = 0; s < ns; s++) {
        float a = ash[s];
        const float* row = eb + (size_t)s * Hh;
        a0 += a * row[tid];
        a1 += a * row[tid + 256];
        a2 += a * row[tid + 512];
        a3 += a * row[tid + 768];
    }
    atomicAdd(&wsum[b * Hh + tid],       a0);
    atomicAdd(&wsum[b * Hh + tid + 256], a1);
    atomicAdd(&wsum[b * Hh + tid + 512], a2);
    atomicAdd(&wsum[b * Hh + tid + 768], a3);
}

// ---------------- scatter-max ----------------
__global__ void scatter_kernel(const float* __restrict__ energy, const int* __restrict__ ext_x,
                               unsigned* __restrict__ scat)
{
    int b = blockIdx.x;
    int s = threadIdx.x;
    if (s < Ss) {
        float e = energy[b * Ss + s];
        int tok = ext_x[b * Ss + s];
        atomicMax(&scat[(size_t)b * VE + tok], fenc(e));
    }
}

// ---------------- host ----------------
extern "C" void kernel_launch(void* const* d_in, const int* in_sizes, int n_in,
                              void* d_out, int out_size)
{
    const int*   y        = (const int*)d_in[0];
    const int*   ext_x    = (const int*)d_in[1];
    const float* prev_h   = (const float*)d_in[2];
    const float* prev_c   = (const float*)d_in[3];
    const float* prev_ctx = (const float*)d_in[4];
    const float* enc      = (const float*)d_in[5];
    const unsigned int* mask = (const unsigned int*)d_in[6];
    const float* dec_out  = (const float*)d_in[7];
    const float* emb      = (const float*)d_in[8];
    const float* W_enc    = (const float*)d_in[9];
    const float* b_enc    = (const float*)d_in[10];
    const float* W_comb   = (const float*)d_in[11];
    const float* b_comb   = (const float*)d_in[12];
    const float* W_red    = (const float*)d_in[13];
    const float* b_red    = (const float*)d_in[14];
    const float* W_ih     = (const float*)d_in[15];
    const float* W_hh     = (const float*)d_in[16];
    const float* b_ih     = (const float*)d_in[17];
    const float* b_hh     = (const float*)d_in[18];
    const float* W_cat    = (const float*)d_in[19];
    const float* b_cat    = (const float*)d_in[20];
    const float* W_logit  = (const float*)d_in[21];
    const float* b_logit  = (const float*)d_in[22];
    float* out = (float*)d_out;

    float *pooled_raw, *pooled_feat, *catA1, *combined, *catA2, *xv, *gates, *hs;
    float *gvec, *energy, *attn, *wsum, *catHC, *logit_in;
    unsigned* scat;
    cudaGetSymbolAddress((void**)&pooled_raw,  g_pooled_raw);
    cudaGetSymbolAddress((void**)&pooled_feat, g_pooled_feat);
    cudaGetSymbolAddress((void**)&catA1,       g_catA1);
    cudaGetSymbolAddress((void**)&combined,    g_combined);
    cudaGetSymbolAddress((void**)&catA2,       g_catA2);
    cudaGetSymbolAddress((void**)&xv,          g_x);
    cudaGetSymbolAddress((void**)&gates,       g_gates);
    cudaGetSymbolAddress((void**)&hs,          g_h);
    cudaGetSymbolAddress((void**)&gvec,        g_gvec);
    cudaGetSymbolAddress((void**)&energy,      g_energy);
    cudaGetSymbolAddress((void**)&attn,        g_attn);
    cudaGetSymbolAddress((void**)&wsum,        g_wsum);
    cudaGetSymbolAddress((void**)&catHC,       g_catHC);
    cudaGetSymbolAddress((void**)&logit_in,    g_logit_in);
    cudaGetSymbolAddress((void**)&scat,        g_scat);

    const size_t O1 = (size_t)Bb * VE;
    const size_t O2 = O1 + (size_t)Bb * Hh;
    const size_t O3 = O2 + (size_t)Bb * Hh;

    // 0) all initializations in one kernel
    const int initN = Bb * VE + Bb * Hh + Bb * Ee + Bb * Ee + Bb * 4 * Hh
                    + Bb * Hh + Bb * Hh + Bb * Hh + Bb * Hh;
    init_all_kernel<<<(initN + 255) / 256, 256>>>(scat, pooled_feat, combined, xv, gates,
                                                  gvec, catHC, logit_in, wsum,
                                                  b_enc, b_comb, b_red, b_ih, b_hh, b_cat);
    // 1) pool encoder outputs
    pool_kernel<<<dim3(Hh / 256, Bb), 256>>>(enc, pooled_raw);
    // 2) pooled_feat += pooled_raw @ W_enc
    gemm_splitk2<false><<<dim3(8, 32), 128>>>(pooled_raw, W_enc, pooled_feat, Hh, Hh, 32, Hh);
    // 3) catA1
    pack1_kernel<<<Bb, 256>>>(y, emb, pooled_feat, dec_out, catA1);
    // 4) combined += catA1 @ W_comb
    gemm_splitk2<false><<<dim3(3, 51), 128>>>(catA1, W_comb, combined, Ee, 1624, 32, Ee);
    // 5) catA2
    pack2_kernel<<<Bb, 256>>>(combined, prev_ctx, catA2);
    // 6) x += catA2 @ W_red
    gemm_splitk2<false><<<dim3(3, 42), 128>>>(catA2, W_red, xv, Ee, 1324, 32, Ee);
    // 7) gates += x @ W_ih ; gates += h0 @ W_hh
    gemm_splitk2<false><<<dim3(32, 4), 128>>>(xv, W_ih, gates, 4 * Hh, Ee, 80, 4 * Hh);
    gemm_splitk2<false><<<dim3(32, 16), 128>>>(prev_h, W_hh, gates, 4 * Hh, Hh, 64, 4 * Hh);
    // 8) LSTM pointwise (h, c, catHC left)
    lstm_kernel<<<(Bb * Hh + 255) / 256, 256>>>(gates, prev_c, hs, out + O1, out + O2, catHC);
    // 9) gvec += h @ W_enc^T
    gemm_splitk2<true><<<dim3(8, 32), 128>>>(hs, W_enc, gvec, Hh, Hh, 32, Hh);
    // 10) attention
    energy_kernel<<<dim3(13, Bb), 256>>>(enc, gvec, hs, b_enc, mask, energy);
    scatter_kernel<<<Bb, Ss>>>(energy, ext_x, scat);
    softmax_kernel<<<Bb, 512>>>(energy, attn);
    wsum_kernel<<<dim3(13, Bb), 256>>>(enc, attn, wsum);
    // 11) catHC right half += wsum @ W_enc (bias pre-initialized)
    gemm_splitk2<false><<<dim3(8, 32), 128>>>(wsum, W_enc, catHC + Hh, Hh, Hh, 32, 2 * Hh);
    // 12) logit_in += catHC @ W_cat
    gemm_splitk2<false><<<dim3(8, 32), 128>>>(catHC, W_cat, logit_in, Hh, 2 * Hh, 64, Hh);
    // 13) tanh + context output
    tanh_ctx_kernel<<<(Bb * Hh + 255) / 256, 256>>>(logit_in, catHC, out + O3);
    // 14) logit GEMM + fused combine
    logit_gemm_kernel<<<(Vv + 127) / 128, 128>>>(logit_in, W_logit, b_logit, scat, out);
    // 15) OOV tail
    oov_kernel<<<(Bb * NOOV + 255) / 256, 256>>>(scat, out);
}

// round 5
// speedup vs baseline: 5.1878x; 1.2805x over previous
#include <cuda_runtime.h>
#include <cuda_bf16.h>
#include <math.h>

#define Bb 64
#define Ss 400
#define Hh 1024
#define Ee 300
#define Vv 50000
#define NOOV 50
#define VE 50050
#define NEGINF (-1e12f)

typedef unsigned long long ull;

// ---------------- scratch ----------------
__device__ float    g_pooled_raw[Bb*Hh];
__device__ float    g_pooled_feat[Bb*Hh];
__device__ float    g_catA1[Bb*1624];
__device__ float    g_combined[Bb*Ee];
__device__ float    g_catA2[Bb*1324];
__device__ float    g_x[Bb*Ee];
__device__ float    g_gates[Bb*4*Hh];
__device__ float    g_h[Bb*Hh];
__device__ float    g_gvec[Bb*Hh];
__device__ float    g_energy[Bb*Ss];
__device__ float    g_attn[Bb*Ss];
__device__ float    g_wsum[Bb*Hh];
__device__ float    g_catHC[Bb*2*Hh];
__device__ float    g_logit_in[Bb*Hh];
__device__ __nv_bfloat16 g_A2[Bb*Hh];          // bf16 tanh(logit_in) for tensor-core GEMM
__device__ unsigned g_scat[(size_t)Bb*VE];

// ---------------- helpers ----------------
__device__ __forceinline__ unsigned fenc(float f) {
    unsigned u = __float_as_uint(f);
    return (u & 0x80000000u) ? ~u : (u | 0x80000000u);
}
__device__ __forceinline__ float fdec(unsigned u) {
    return (u & 0x80000000u) ? __uint_as_float(u & 0x7fffffffu) : __uint_as_float(~u);
}
__device__ __forceinline__ float sigmf(float x) { return 1.f / (1.f + expf(-x)); }

__device__ __forceinline__ void ffma2(ull& d, ull a, ull b) {
    asm("fma.rn.f32x2 %0, %1, %2, %0;" : "+l"(d) : "l"(a), "l"(b));
}
__device__ __forceinline__ ull dup2(float x) {
    ull d; asm("mov.b64 %0, {%1, %1};" : "=l"(d) : "f"(x)); return d;
}
__device__ __forceinline__ void unpack2(ull v, float& lo, float& hi) {
    asm("mov.b64 {%0, %1}, %2;" : "=f"(lo), "=f"(hi) : "l"(v));
}
// pack two f32 -> bf16x2 (lo in low half)
__device__ __forceinline__ unsigned cvt2(float lo, float hi) {
    unsigned r;
    asm("cvt.rn.bf16x2.f32 %0, %1, %2;" : "=r"(r) : "f"(hi), "f"(lo));
    return r;
}
__device__ __forceinline__ void mma_bf16(float& c0, float& c1, float& c2, float& c3,
                                         unsigned a0, unsigned a1, unsigned a2, unsigned a3,
                                         unsigned b0, unsigned b1) {
    asm("mma.sync.aligned.m16n8k16.row.col.f32.bf16.bf16.f32 "
        "{%0,%1,%2,%3}, {%4,%5,%6,%7}, {%8,%9}, {%0,%1,%2,%3};"
        : "+f"(c0), "+f"(c1), "+f"(c2), "+f"(c3)
        : "r"(a0), "r"(a1), "r"(a2), "r"(a3), "r"(b0), "r"(b1));
}

// ---------------- init everything up front (one kernel) ----------------
__global__ void init_all_kernel(unsigned* __restrict__ scat,
                                float* __restrict__ pooled_feat, float* __restrict__ combined,
                                float* __restrict__ xv, float* __restrict__ gates,
                                float* __restrict__ gvec, float* __restrict__ catHC,
                                float* __restrict__ logit_in, float* __restrict__ wsum,
                                const float* __restrict__ b_enc, const float* __restrict__ b_comb,
                                const float* __restrict__ b_red, const float* __restrict__ b_ih,
                                const float* __restrict__ b_hh, const float* __restrict__ b_cat)
{
    int i = blockIdx.x * 256 + threadIdx.x;
    const int S0 = Bb * VE;
    if (i < S0) { scat[i] = fenc(NEGINF); return; }
    i -= S0;
    if (i < Bb * Hh) { pooled_feat[i] = b_enc[i & 1023]; return; }
    i -= Bb * Hh;
    if (i < Bb * Ee) { combined[i] = b_comb[i % Ee]; return; }
    i -= Bb * Ee;
    if (i < Bb * Ee) { xv[i] = b_red[i % Ee]; return; }
    i -= Bb * Ee;
    if (i < Bb * 4 * Hh) { int n = i & 4095; gates[i] = b_ih[n] + b_hh[n]; return; }
    i -= Bb * 4 * Hh;
    if (i < Bb * Hh) { gvec[i] = 0.f; return; }
    i -= Bb * Hh;
    if (i < Bb * Hh) { catHC[(size_t)(i >> 10) * 2048 + 1024 + (i & 1023)] = b_enc[i & 1023]; return; }
    i -= Bb * Hh;
    if (i < Bb * Hh) { logit_in[i] = b_cat[i & 1023]; return; }
    i -= Bb * Hh;
    if (i < Bb * Hh) { wsum[i] = 0.f; return; }
}

// ---------------- split-K skinny GEMM v2: prefetched, FFMA2, atomic accumulate ----------------
template<bool TRANSB>
__global__ __launch_bounds__(128)
void gemm_splitk2(const float* __restrict__ A, const float* __restrict__ Bm,
                  float* __restrict__ C, int N, int K, int KC, int ldc)
{
    __shared__ float As[16][64];
    __shared__ float Bs[16][128];
    const int tid = threadIdx.x;
    const int tx = tid & 15, ty = tid >> 4;
    const int n0 = blockIdx.x * 128;
    const int kc0 = blockIdx.y * KC;
    const int kend = min(kc0 + KC, K);
    const int ntiles = (kend - kc0 + 15) >> 4;

    const int am = tid >> 2;
    const int ak = (tid & 3) << 2;
    const int bk = (tid & 3) << 2;
    const int bnb = tid >> 2;

    ull acc[8][4];
#pragma unroll
    for (int i = 0; i < 8; i++)
#pragma unroll
        for (int j = 0; j < 4; j++) acc[i][j] = 0ull;

    float4 aR0, aR1, bR[4];

    auto loadTile = [&](int k0) {
        if (k0 + 16 <= kend) {
            aR0 = *reinterpret_cast<const float4*>(&A[(size_t)am * K + k0 + ak]);
            aR1 = *reinterpret_cast<const float4*>(&A[(size_t)(am + 32) * K + k0 + ak]);
        } else {
            float v[4], w[4];
#pragma unroll
            for (int l = 0; l < 4; l++) {
                int k = k0 + ak + l;
                v[l] = (k < kend) ? A[(size_t)am * K + k] : 0.f;
                w[l] = (k < kend) ? A[(size_t)(am + 32) * K + k] : 0.f;
            }
            aR0 = make_float4(v[0], v[1], v[2], v[3]);
            aR1 = make_float4(w[0], w[1], w[2], w[3]);
        }
        if (!TRANSB) {
            if (k0 + 16 <= kend && n0 + 128 <= N) {
#pragma unroll
                for (int j = 0; j < 4; j++) {
                    int i = tid + j * 128;
                    int kk = i >> 5, nq = (i & 31) << 2;
                    bR[j] = *reinterpret_cast<const float4*>(&Bm[(size_t)(k0 + kk) * N + n0 + nq]);
                }
            } else {
#pragma unroll
                for (int j = 0; j < 4; j++) {
                    int i = tid + j * 128;
                    int kk = i >> 5, nq = (i & 31) << 2;
                    float v[4];
#pragma unroll
                    for (int l = 0; l < 4; l++) {
                        int k = k0 + kk, n = n0 + nq + l;
                        v[l] = (k < kend && n < N) ? Bm[(size_t)k * N + n] : 0.f;
                    }
                    bR[j] = make_float4(v[0], v[1], v[2], v[3]);
                }
            }
        } else {
            if (k0 + 16 <= kend && n0 + 128 <= N) {
#pragma unroll
                for (int j = 0; j < 4; j++) {
                    int bn = bnb + 32 * j;
                    bR[j] = *reinterpret_cast<const float4*>(&Bm[(size_t)(n0 + bn) * K + k0 + bk]);
                }
            } else {
#pragma unroll
                for (int j = 0; j < 4; j++) {
                    int bn = bnb + 32 * j;
                    float v[4];
#pragma unroll
                    for (int l = 0; l < 4; l++) {
                        int k = k0 + bk + l;
                        v[l] = (n0 + bn < N && k < kend) ? Bm[(size_t)(n0 + bn) * K + k] : 0.f;
                    }
                    bR[j] = make_float4(v[0], v[1], v[2], v[3]);
                }
            }
        }
    };

    auto storeTile = [&]() {
        As[ak + 0][am] = aR0.x; As[ak + 1][am] = aR0.y;
        As[ak + 2][am] = aR0.z; As[ak + 3][am] = aR0.w;
        As[ak + 0][am + 32] = aR1.x; As[ak + 1][am + 32] = aR1.y;
        As[ak + 2][am + 32] = aR1.z; As[ak + 3][am + 32] = aR1.w;
        if (!TRANSB) {
#pragma unroll
            for (int j = 0; j < 4; j++) {
                int i = tid + j * 128;
                int kk = i >> 5, nq = (i & 31) << 2;
                *reinterpret_cast<float4*>(&Bs[kk][nq]) = bR[j];
            }
        } else {
#pragma unroll
            for (int j = 0; j < 4; j++) {
                int bn = bnb + 32 * j;
                Bs[bk + 0][bn] = bR[j].x; Bs[bk + 1][bn] = bR[j].y;
                Bs[bk + 2][bn] = bR[j].z; Bs[bk + 3][bn] = bR[j].w;
            }
        }
    };

    loadTile(kc0);
    storeTile();
    __syncthreads();

    for (int t = 0; t < ntiles; t++) {
        if (t + 1 < ntiles) loadTile(kc0 + (t + 1) * 16);
#pragma unroll
        for (int kk = 0; kk < 16; kk++) {
            float4 av0 = *reinterpret_cast<const float4*>(&As[kk][ty * 8]);
            float4 av1 = *reinterpret_cast<const float4*>(&As[kk][ty * 8 + 4]);
            ull ad[8];
            ad[0] = dup2(av0.x); ad[1] = dup2(av0.y); ad[2] = dup2(av0.z); ad[3] = dup2(av0.w);
            ad[4] = dup2(av1.x); ad[5] = dup2(av1.y); ad[6] = dup2(av1.z); ad[7] = dup2(av1.w);
            ulonglong2 b01 = *reinterpret_cast<const ulonglong2*>(&Bs[kk][tx * 8]);
            ulonglong2 b23 = *reinterpret_cast<const ulonglong2*>(&Bs[kk][tx * 8 + 4]);
            ull bp[4] = {b01.x, b01.y, b23.x, b23.y};
#pragma unroll
            for (int i = 0; i < 8; i++)
#pragma unroll
                for (int j = 0; j < 4; j++) ffma2(acc[i][j], ad[i], bp[j]);
        }
        if (t + 1 < ntiles) {
            __syncthreads();
            storeTile();
            __syncthreads();
        }
    }

#pragma unroll
    for (int i = 0; i < 8; i++) {
        int m = ty * 8 + i;
#pragma unroll
        for (int j = 0; j < 4; j++) {
            float lo, hi;
            unpack2(acc[i][j], lo, hi);
            int n = n0 + tx * 8 + 2 * j;
            if (n < N)     atomicAdd(&C[(size_t)m * ldc + n], lo);
            if (n + 1 < N) atomicAdd(&C[(size_t)m * ldc + n + 1], hi);
        }
    }
}

// ---------------- logit GEMM via bf16 tensor cores + fused combine epilogue ----------------
// out[64, n] = combine( A2[64,1024](bf16) @ W[1024,50000](fp32->bf16 otf) + bias, scat )
// BM=64, BN=128, BK=32; 256 threads = 8 warps: warp_m = w>>1 (16 rows), warp_n = w&1 (64 cols)
__global__ __launch_bounds__(256)
void logit_mma_kernel(const unsigned* __restrict__ A2u,   // bf16x2 pairs, [64][512]
                      const float* __restrict__ W,
                      const float* __restrict__ bias, const unsigned* __restrict__ scat,
                      float* __restrict__ out)
{
    __shared__ unsigned Bs2[16][136];   // [k-pair][n] bf16x2, padded stride 136
    const int tid = threadIdx.x;
    const int lane = tid & 31, wid = tid >> 5;
    const int warp_m = wid >> 1, warp_n = wid & 1;
    const int g = lane >> 2, tc = lane & 3;
    const int n0 = blockIdx.x * 128;

    // W loading coords: pair-row pr (0..15), n4 = 8-col group
    const int pr = tid >> 4;            // 0..15
    const int n4 = (tid & 15) * 8;      // 0..120
    const bool full = (n0 + 128 <= Vv);

    float4 w00, w01, w10, w11;          // two k rows x 8 cols
    auto loadW = [&](int k0) {
        const float* r0 = W + (size_t)(k0 + 2 * pr) * Vv + n0 + n4;
        const float* r1 = r0 + Vv;
        if (full) {
            w00 = *reinterpret_cast<const float4*>(r0);
            w01 = *reinterpret_cast<const float4*>(r0 + 4);
            w10 = *reinterpret_cast<const float4*>(r1);
            w11 = *reinterpret_cast<const float4*>(r1 + 4);
        } else {
            float v0[8], v1[8];
#pragma unroll
            for (int l = 0; l < 8; l++) {
                bool ok = (n0 + n4 + l) < Vv;
                v0[l] = ok ? r0[l] : 0.f;
                v1[l] = ok ? r1[l] : 0.f;
            }
            w00 = make_float4(v0[0], v0[1], v0[2], v0[3]);
            w01 = make_float4(v0[4], v0[5], v0[6], v0[7]);
            w10 = make_float4(v1[0], v1[1], v1[2], v1[3]);
            w11 = make_float4(v1[4], v1[5], v1[6], v1[7]);
        }
    };
    auto storeW = [&]() {
        uint4 p0, p1;
        p0.x = cvt2(w00.x, w10.x); p0.y = cvt2(w00.y, w10.y);
        p0.z = cvt2(w00.z, w10.z); p0.w = cvt2(w00.w, w10.w);
        p1.x = cvt2(w01.x, w11.x); p1.y = cvt2(w01.y, w11.y);
        p1.z = cvt2(w01.z, w11.z); p1.w = cvt2(w01.w, w11.w);
        *reinterpret_cast<uint4*>(&Bs2[pr][n4])     = p0;
        *reinterpret_cast<uint4*>(&Bs2[pr][n4 + 4]) = p1;
    };

    float acc[8][4];
#pragma unroll
    for (int nt = 0; nt < 8; nt++)
#pragma unroll
        for (int c = 0; c < 4; c++) acc[nt][c] = 0.f;

    // A row base pointers (bf16 pairs; stays hot in L1/L2)
    const unsigned* pA  = A2u + (size_t)(warp_m * 16 + g) * 512;
    const unsigned* pA8 = pA + 8 * 512;

    loadW(0);
    storeW();
    __syncthreads();

    for (int t = 0; t < 32; t++) {
        if (t < 31) loadW((t + 1) * 32);
        const int kpb = t * 16;   // k-pair base of this tile
#pragma unroll
        for (int ks = 0; ks < 2; ks++) {
            unsigned a0 = pA [kpb + ks * 8 + tc];
            unsigned a1 = pA8[kpb + ks * 8 + tc];
            unsigned a2 = pA [kpb + ks * 8 + 4 + tc];
            unsigned a3 = pA8[kpb + ks * 8 + 4 + tc];
#pragma unroll
            for (int nt = 0; nt < 8; nt++) {
                int nn = warp_n * 64 + nt * 8 + g;
                unsigned b0 = Bs2[ks * 8 + tc][nn];
                unsigned b1 = Bs2[ks * 8 + 4 + tc][nn];
                mma_bf16(acc[nt][0], acc[nt][1], acc[nt][2], acc[nt][3],
                         a0, a1, a2, a3, b0, b1);
            }
        }
        if (t < 31) {
            __syncthreads();
            storeW();
            __syncthreads();
        }
    }

    // fused combine epilogue
#pragma unroll
    for (int nt = 0; nt < 8; nt++) {
        int cb = n0 + warp_n * 64 + nt * 8 + tc * 2;
#pragma unroll
        for (int half = 0; half < 2; half++) {
            int m = warp_m * 16 + g + half * 8;
#pragma unroll
            for (int c = 0; c < 2; c++) {
                int n = cb + c;
                if (n >= Vv) continue;
                float v = acc[nt][half * 2 + c] + bias[n];
                float sc = fdec(scat[(size_t)m * VE + n]);
                if (sc == NEGINF) sc = 0.f;
                float o = v + sc;
                if (o == NEGINF) o = 0.f;
                if (n == 1) o = NEGINF;
                out[(size_t)m * VE + n] = o;
            }
        }
    }
}

// ---------------- pool ----------------
__global__ void pool_kernel(const float* __restrict__ enc, float* __restrict__ out)
{
    int b = blockIdx.y;
    int h = blockIdx.x * 256 + threadIdx.x;
    const float* p = enc + (size_t)b * Ss * Hh + h;
    float a0 = 0.f, a1 = 0.f, a2 = 0.f, a3 = 0.f;
    for (int s = 0; s < Ss; s += 4) {
        a0 += p[(size_t)(s + 0) * Hh];
        a1 += p[(size_t)(s + 1) * Hh];
        a2 += p[(size_t)(s + 2) * Hh];
        a3 += p[(size_t)(s + 3) * Hh];
    }
    out[b * Hh + h] = (a0 + a1 + a2 + a3) * (1.0f / Ss);
}

// ---------------- pack kernels ----------------
__global__ void pack1_kernel(const int* __restrict__ y, const float* __restrict__ emb,
                             const float* __restrict__ pooled, const float* __restrict__ dec,
                             float* __restrict__ out)
{
    int b = blockIdx.y;
    int i = blockIdx.x * 256 + threadIdx.x;
    if (i >= 1624) return;
    int yy = y[b];
    float v;
    if (i < Ee)           v = emb[(size_t)yy * Ee + i];
    else if (i < Ee + Hh) v = pooled[b * Hh + (i - Ee)];
    else                  v = dec[b * Ee + (i - Ee - Hh)];
    out[b * 1624 + i] = v;
}

__global__ void pack2_kernel(const float* __restrict__ comb, const float* __restrict__ pctx,
                             float* __restrict__ out)
{
    int b = blockIdx.y;
    int i = blockIdx.x * 256 + threadIdx.x;
    if (i >= 1324) return;
    out[b * 1324 + i] = (i < Ee) ? comb[b * Ee + i] : pctx[b * Hh + (i - Ee)];
}

// ---------------- LSTM pointwise (also fills catHC left half) ----------------
__global__ void lstm_kernel(const float* __restrict__ gates, const float* __restrict__ c0,
                            float* __restrict__ hs, float* __restrict__ dh, float* __restrict__ dc,
                            float* __restrict__ catHC)
{
    int idx = blockIdx.x * 256 + threadIdx.x;
    if (idx >= Bb * Hh) return;
    int b = idx >> 10, j = idx & (Hh - 1);
    const float* gb = gates + (size_t)b * 4 * Hh;
    float gi = gb[j], gf = gb[Hh + j], gg = gb[2 * Hh + j], go = gb[3 * Hh + j];
    float c = sigmf(gf) * c0[idx] + sigmf(gi) * tanhf(gg);
    float h = sigmf(go) * tanhf(c);
    hs[idx] = h; dh[idx] = h; dc[idx] = c;
    catHC[(size_t)b * 2048 + j] = h;
}

// ---------------- tanh(logit_in)->bf16 A2, context->out, OOV tail ----------------
__global__ void tanh_ctx_kernel(const float* __restrict__ li, __nv_bfloat16* __restrict__ A2,
                                const float* __restrict__ catHC, float* __restrict__ out_ctx,
                                const unsigned* __restrict__ scat, float* __restrict__ out)
{
    int i = blockIdx.x * 256 + threadIdx.x;
    if (i < Bb * Hh) {
        A2[i] = __float2bfloat16(tanhf(li[i]));
        out_ctx[i] = catHC[(size_t)(i >> 10) * 2048 + 1024 + (i & 1023)];
        return;
    }
    i -= Bb * Hh;
    if (i < Bb * NOOV) {
        int b = i / NOOV, v = Vv + i % NOOV;
        float sc = fdec(scat[(size_t)b * VE + v]);
        if (sc == NEGINF) sc = 0.f;
        float o = sc;
        if (o == NEGINF) o = 0.f;
        out[(size_t)b * VE + v] = o;
    }
}

// ---------------- attention: phase 1, energies (grid: 13 x 64) ----------------
__global__ __launch_bounds__(256)
void energy_kernel(const float* __restrict__ enc, const float* __restrict__ gv,
                   const float* __restrict__ hv, const float* __restrict__ benc,
                   const unsigned int* __restrict__ mask, float* __restrict__ energy)
{
    int b = blockIdx.y, chunk = blockIdx.x;
    int tid = threadIdx.x, warp = tid >> 5, lane = tid & 31;
    __shared__ float gsh[Hh];
    __shared__ float red[8];
    __shared__ float sh_hb;

    *reinterpret_cast<float4*>(&gsh[tid * 4]) =
        *reinterpret_cast<const float4*>(&gv[b * Hh + tid * 4]);

    float p = 0.f;
#pragma unroll
    for (int j = 0; j < 4; j++) {
        int i = tid + 256 * j;
        p += hv[b * Hh + i] * benc[i];
    }
    for (int o = 16; o; o >>= 1) p += __shfl_xor_sync(0xffffffffu, p, o);
    if (lane == 0) red[warp] = p;
    __syncthreads();
    if (tid == 0) {
        float v = 0.f;
#pragma unroll
        for (int w = 0; w < 8; w++) v += red[w];
        sh_hb = v;
    }
    __syncthreads();
    float hb = sh_hb;

    const float* eb = enc + (size_t)b * Ss * Hh;
#pragma unroll
    for (int it = 0; it < 4; it++) {
        int s = chunk * 32 + it * 8 + warp;
        if (s >= Ss) break;
        const float* row = eb + (size_t)s * Hh;
        float acc = 0.f;
#pragma unroll 8
        for (int i = lane; i < Hh; i += 32) acc += row[i] * gsh[i];
        for (int o = 16; o; o >>= 1) acc += __shfl_xor_sync(0xffffffffu, acc, o);
        if (lane == 0)
            energy[b * Ss + s] = (mask[b * Ss + s] != 0u) ? NEGINF : (acc + hb);
    }
}

// ---------------- attention: phase 2, softmax + scatter-max (grid: 64) ----------------
__global__ __launch_bounds__(512)
void softmax_scatter_kernel(const float* __restrict__ energy, float* __restrict__ attn,
                            const int* __restrict__ ext_x, unsigned* __restrict__ scat)
{
    int b = blockIdx.x;
    int tid = threadIdx.x, warp = tid >> 5, lane = tid & 31;
    __shared__ float esh[Ss];
    __shared__ float red[16];
    __shared__ float sh_mx, sh_sum;

    float e = (tid < Ss) ? energy[b * Ss + tid] : -3.4e38f;
    if (tid < Ss) {
        esh[tid] = e;
        atomicMax(&scat[(size_t)b * VE + ext_x[b * Ss + tid]], fenc(e));
    }

    float m = e;
    for (int o = 16; o; o >>= 1) m = fmaxf(m, __shfl_xor_sync(0xffffffffu, m, o));
    if (lane == 0) red[warp] = m;
    __syncthreads();
    if (warp == 0) {
        float v = (lane < 16) ? red[lane] : -3.4e38f;
        for (int o = 8; o; o >>= 1) v = fmaxf(v, __shfl_xor_sync(0xffffffffu, v, o));
        if (lane == 0) sh_mx = v;
    }
    __syncthreads();
    float mx = sh_mx;

    float pe = 0.f;
    if (tid < Ss) pe = expf(esh[tid] - mx);
    float sm = pe;
    for (int o = 16; o; o >>= 1) sm += __shfl_xor_sync(0xffffffffu, sm, o);
    if (lane == 0) red[warp] = sm;
    __syncthreads();
    if (warp == 0) {
        float v = (lane < 16) ? red[lane] : 0.f;
        for (int o = 8; o; o >>= 1) v += __shfl_xor_sync(0xffffffffu, v, o);
        if (lane == 0) sh_sum = v;
    }
    __syncthreads();
    if (tid < Ss) attn[b * Ss + tid] = pe / sh_sum;
}

// ---------------- attention: phase 3, wsum accumulation (grid: 13 x 64) ----------------
__global__ __launch_bounds__(256)
void wsum_kernel(const float* __restrict__ enc, const float* __restrict__ attn,
                 float* __restrict__ wsum)
{
    int b = blockIdx.y, chunk = blockIdx.x;
    int tid = threadIdx.x;
    int s0 = chunk * 32;
    int ns = min(32, Ss - s0);
    __shared__ float ash[32];
    if (tid < 32) ash[tid] = (tid < ns) ? attn[b * Ss + s0 + tid] : 0.f;
    __syncthreads();

    const float* eb = enc + (size_t)b * Ss * Hh + (size_t)s0 * Hh;
    float a0 = 0.f, a1 = 0.f, a2 = 0.f, a3 = 0.f;
    for (int s = 0; s < ns; s++) {
        float a = ash[s];
        const float* row = eb + (size_t)s * Hh;
        a0 += a * row[tid];
        a1 += a * row[tid + 256];
        a2 += a * row[tid + 512];
        a3 += a * row[tid + 768];
    }
    atomicAdd(&wsum[b * Hh + tid],       a0);
    atomicAdd(&wsum[b * Hh + tid + 256], a1);
    atomicAdd(&wsum[b * Hh + tid + 512], a2);
    atomicAdd(&wsum[b * Hh + tid + 768], a3);
}

// ---------------- host ----------------
extern "C" void kernel_launch(void* const* d_in, const int* in_sizes, int n_in,
                              void* d_out, int out_size)
{
    const int*   y        = (const int*)d_in[0];
    const int*   ext_x    = (const int*)d_in[1];
    const float* prev_h   = (const float*)d_in[2];
    const float* prev_c   = (const float*)d_in[3];
    const float* prev_ctx = (const float*)d_in[4];
    const float* enc      = (const float*)d_in[5];
    const unsigned int* mask = (const unsigned int*)d_in[6];
    const float* dec_out  = (const float*)d_in[7];
    const float* emb      = (const float*)d_in[8];
    const float* W_enc    = (const float*)d_in[9];
    const float* b_enc    = (const float*)d_in[10];
    const float* W_comb   = (const float*)d_in[11];
    const float* b_comb   = (const float*)d_in[12];
    const float* W_red    = (const float*)d_in[13];
    const float* b_red    = (const float*)d_in[14];
    const float* W_ih     = (const float*)d_in[15];
    const float* W_hh     = (const float*)d_in[16];
    const float* b_ih     = (const float*)d_in[17];
    const float* b_hh     = (const float*)d_in[18];
    const float* W_cat    = (const float*)d_in[19];
    const float* b_cat    = (const float*)d_in[20];
    const float* W_logit  = (const float*)d_in[21];
    const float* b_logit  = (const float*)d_in[22];
    float* out = (float*)d_out;

    float *pooled_raw, *pooled_feat, *catA1, *combined, *catA2, *xv, *gates, *hs;
    float *gvec, *energy, *attn, *wsum, *catHC, *logit_in;
    __nv_bfloat16* A2;
    unsigned* scat;
    cudaGetSymbolAddress((void**)&pooled_raw,  g_pooled_raw);
    cudaGetSymbolAddress((void**)&pooled_feat, g_pooled_feat);
    cudaGetSymbolAddress((void**)&catA1,       g_catA1);
    cudaGetSymbolAddress((void**)&combined,    g_combined);
    cudaGetSymbolAddress((void**)&catA2,       g_catA2);
    cudaGetSymbolAddress((void**)&xv,          g_x);
    cudaGetSymbolAddress((void**)&gates,       g_gates);
    cudaGetSymbolAddress((void**)&hs,          g_h);
    cudaGetSymbolAddress((void**)&gvec,        g_gvec);
    cudaGetSymbolAddress((void**)&energy,      g_energy);
    cudaGetSymbolAddress((void**)&attn,        g_attn);
    cudaGetSymbolAddress((void**)&wsum,        g_wsum);
    cudaGetSymbolAddress((void**)&catHC,       g_catHC);
    cudaGetSymbolAddress((void**)&logit_in,    g_logit_in);
    cudaGetSymbolAddress((void**)&A2,          g_A2);
    cudaGetSymbolAddress((void**)&scat,        g_scat);

    const size_t O1 = (size_t)Bb * VE;
    const size_t O2 = O1 + (size_t)Bb * Hh;
    const size_t O3 = O2 + (size_t)Bb * Hh;

    const int initN = Bb * VE + Bb * Hh + Bb * Ee + Bb * Ee + Bb * 4 * Hh
                    + Bb * Hh + Bb * Hh + Bb * Hh + Bb * Hh;
    init_all_kernel<<<(initN + 255) / 256, 256>>>(scat, pooled_feat, combined, xv, gates,
                                                  gvec, catHC, logit_in, wsum,
                                                  b_enc, b_comb, b_red, b_ih, b_hh, b_cat);
    pool_kernel<<<dim3(Hh / 256, Bb), 256>>>(enc, pooled_raw);
    gemm_splitk2<false><<<dim3(8, 32), 128>>>(pooled_raw, W_enc, pooled_feat, Hh, Hh, 32, Hh);
    pack1_kernel<<<dim3(7, Bb), 256>>>(y, emb, pooled_feat, dec_out, catA1);
    gemm_splitk2<false><<<dim3(3, 51), 128>>>(catA1, W_comb, combined, Ee, 1624, 32, Ee);
    pack2_kernel<<<dim3(6, Bb), 256>>>(combined, prev_ctx, catA2);
    gemm_splitk2<false><<<dim3(3, 42), 128>>>(catA2, W_red, xv, Ee, 1324, 32, Ee);
    gemm_splitk2<false><<<dim3(32, 4), 128>>>(xv, W_ih, gates, 4 * Hh, Ee, 80, 4 * Hh);
    gemm_splitk2<false><<<dim3(32, 16), 128>>>(prev_h, W_hh, gates, 4 * Hh, Hh, 64, 4 * Hh);
    lstm_kernel<<<(Bb * Hh + 255) / 256, 256>>>(gates, prev_c, hs, out + O1, out + O2, catHC);
    gemm_splitk2<true><<<dim3(8, 32), 128>>>(hs, W_enc, gvec, Hh, Hh, 32, Hh);
    energy_kernel<<<dim3(13, Bb), 256>>>(enc, gvec, hs, b_enc, mask, energy);
    softmax_scatter_kernel<<<Bb, 512>>>(energy, attn, ext_x, scat);
    wsum_kernel<<<dim3(13, Bb), 256>>>(enc, attn, wsum);
    gemm_splitk2<false><<<dim3(8, 32), 128>>>(wsum, W_enc, catHC + Hh, Hh, Hh, 32, 2 * Hh);
    gemm_splitk2<false><<<dim3(8, 32), 128>>>(catHC, W_cat, logit_in, Hh, 2 * Hh, 64, Hh);
    tanh_ctx_kernel<<<(Bb * Hh + Bb * NOOV + 255) / 256, 256>>>(logit_in, A2, catHC, out + O3, scat, out);
    logit_mma_kernel<<<(Vv + 127) / 128, 256>>>((const unsigned*)A2, W_logit, b_logit, scat, out);
}